// round 9
// baseline (speedup 1.0000x reference)
#include <cuda_runtime.h>
#include <math.h>

// ---------------------------------------------------------------------------
// CRF-as-RNN forward — persistent kernel v4.
//  - 296 blocks x 512 threads (2 blocks/SM, 32 warps/SM, <=64 regs)
//  - bilateral: low-rank feature map, degree-4 Taylor, R=126 monomials
//  - bl backprojection: direct per-(class,pair) output, no partials
//  - spatial: separable 33-tap Gaussian on zero-padded buffers (no bounds chk)
// ---------------------------------------------------------------------------

typedef unsigned long long ull;

static constexpr int HW   = 96;
static constexpr int NPIX = HW * HW;        // 9216
static constexpr int NC   = 21;
static constexpr int RD   = 126;            // monomials deg<=4 in 5 vars
static constexpr int GRID = 296;
static constexpr int TPB  = 512;
static constexpr int NTHR = GRID * TPB;     // 151552
static constexpr int KR   = 16;
static constexpr int KW   = 2 * KR + 1;     // 33
static constexpr int NPAIR = NPIX / 2;      // 4608
static constexpr int PXB  = 32;             // pixels/block in pointwise phases
static constexpr int SPAD = 128;            // x-padded row stride
static constexpr int CHPX = 576;            // moments chunk pixels
static constexpr int NCHK = NPIX / CHPX;    // 16
static constexpr int MTASKS = NC * NCHK;    // 336

// ------------------------- device scratch ----------------------------------
__device__ float g_u[NC * NPIX];
__device__ float g_s[NC * NPIX];            // linear s (moments)
__device__ float g_sP[NC * HW * SPAD];      // x-padded s (spX), zero borders
__device__ float g_tmpP[NC * SPAD * HW];    // y-padded tmp (spY), zero borders
__device__ float g_sp[NC * NPIX];
__device__ float g_bl[NC * NPIX];
__device__ float g_ker[KW];
__device__ float g_gsx[HW];
__device__ float g_phiT[(size_t)RD * NPIX]; // 4.6 MB [r][n]
__device__ float g_M0[RD];
__device__ float g_normbl[NPIX];
__device__ float g_mom[NC * RD];            // [c][r]
__device__ float g_W1[NC * NC], g_W2[NC * NC], g_cvec[NC];
__device__ unsigned g_barCount = 0;
__device__ unsigned g_barGen = 0;

// CG-style grid barrier. 296 blocks == 2/SM, all resident: no deadlock.
__device__ __forceinline__ void gsync() {
    __syncthreads();
    if (threadIdx.x == 0) {
        unsigned* cnt = &g_barCount;
        unsigned* gen = &g_barGen;
        unsigned my;
        asm volatile("ld.relaxed.gpu.u32 %0, [%1];" : "=r"(my) : "l"(gen));
        unsigned prev;
        asm volatile("atom.add.release.gpu.u32 %0, [%1], 1;"
                     : "=r"(prev) : "l"(cnt) : "memory");
        if (prev == GRID - 1u) {
            asm volatile("st.relaxed.gpu.u32 [%0], %1;" :: "l"(cnt), "r"(0u));
            asm volatile("st.release.gpu.u32 [%0], %1;"
                         :: "l"(gen), "r"(my + 1u) : "memory");
        } else {
            unsigned cur;
            do {
                __nanosleep(32);
                asm volatile("ld.acquire.gpu.u32 %0, [%1];"
                             : "=r"(cur) : "l"(gen) : "memory");
            } while (cur == my);
        }
    }
    __syncthreads();
}

__device__ __forceinline__ void fma2(ull& acc, ull a, ull b) {
    asm("fma.rn.f32x2 %0, %1, %2, %0;" : "+l"(acc) : "l"(a), "l"(b));
}

__global__ __launch_bounds__(TPB, 2) void crf_all(
    const float* __restrict__ img,
    const float* __restrict__ net_w, const float* __restrict__ net_b,
    const float* __restrict__ sp_w,  const float* __restrict__ sp_b,
    const float* __restrict__ bl_w,  const float* __restrict__ bl_b,
    const float* __restrict__ comp_w,const float* __restrict__ comp_b,
    float* __restrict__ out)
{
    __shared__ __align__(16) char sraw[24576];
    const int tid  = threadIdx.x;
    const int bid  = blockIdx.x;
    const int gtid = bid * TPB + tid;
    const int lane = tid & 31;
    const int gwarp = gtid >> 5;            // 0..4735

    // ======================= phase 0: independent setup =====================
    for (int t = gtid; t < RD; t += NTHR) g_M0[t] = 0.0f;
    for (int t = gtid; t < NC * RD; t += NTHR) g_mom[t] = 0.0f;
    for (int t = gtid; t < NC * HW * SPAD; t += NTHR) { g_sP[t] = 0.0f; g_tmpP[t] = 0.0f; }
    for (int t = gtid; t < KW; t += NTHR) {
        float d = (float)(t - KR) * (1.0f / 3.0f);
        g_ker[t] = expf(-0.5f * d * d);
    }
    for (int t = gtid; t < HW; t += NTHR) {
        float acc = 0.0f;
        for (int d = 0; d < KW; d++) {
            int xx = t + d - KR;
            if (xx >= 0 && xx < HW) {
                float dd = (float)(d - KR) * (1.0f / 3.0f);
                acc += expf(-0.5f * dd * dd);
            }
        }
        g_gsx[t] = acc;
    }
    for (int t = gtid; t < NC * NC; t += NTHR) {
        int o = t / NC, k = t % NC;
        float a1 = 0.0f, a2 = 0.0f;
        for (int c = 0; c < NC; c++) {
            a1 += comp_w[o * NC + c] * sp_w[c * NC + k];
            a2 += comp_w[o * NC + c] * bl_w[c * NC + k];
        }
        g_W1[t] = a1; g_W2[t] = a2;
    }
    for (int t = gtid; t < NC; t += NTHR) {
        float cv = comp_b[t];
        for (int c = 0; c < NC; c++) cv += comp_w[t * NC + c] * (sp_b[c] + bl_b[c]);
        g_cvec[t] = cv;
    }
    // unary 3x3 SAME conv
    for (int t = gtid; t < NC * NPIX; t += NTHR) {
        int o = t / NPIX, n = t % NPIX;
        int y = n / HW, x = n % HW;
        float acc = net_b[o];
        #pragma unroll
        for (int c = 0; c < 3; c++)
            #pragma unroll
            for (int ky = 0; ky < 3; ky++) {
                int yy = y + ky - 1;
                if (yy < 0 || yy >= HW) continue;
                #pragma unroll
                for (int kx = 0; kx < 3; kx++) {
                    int xx = x + kx - 1;
                    if (xx < 0 || xx >= HW) continue;
                    acc += img[c * NPIX + yy * HW + xx] * net_w[((o * 3 + c) * 3 + ky) * 3 + kx];
                }
            }
        g_u[t] = acc;
    }
    gsync();

    // ====== phase 1: build phiT (+M0 via atomics), initial softmax ==========
    {
        // warp-task = (32-px group g<288, r-half tau<2); incremental monomials
        const float S1 = 1.0f, S2 = 0.70710678f, S3 = 0.57735027f, S4 = 0.5f;
        for (int wt = gwarp; wt < 288 * 2; wt += NTHR / 32) {
            int g = wt >> 1, tau = wt & 1;
            int rlo = tau * 63, rhi = rlo + 63;
            int n = g * 32 + lane;
            int y = n / HW, x = n % HW;
            float f0 = ((float)x - 47.5f) * (1.0f / 160.0f);
            float f1 = ((float)y - 47.5f) * (1.0f / 160.0f);
            float f2 = (img[0 * NPIX + n] - 0.5f) * (1.0f / 3.0f);
            float f3 = (img[1 * NPIX + n] - 0.5f) * (1.0f / 3.0f);
            float f4 = (img[2 * NPIX + n] - 0.5f) * (1.0f / 3.0f);
            float a = expf(-0.5f * (f0*f0 + f1*f1 + f2*f2 + f3*f3 + f4*f4));
            int r = 0;
            float v0 = a;
            #pragma unroll
            for (int m0 = 0; m0 <= 4; m0++) {
                float v1 = v0;
                #pragma unroll
                for (int m1 = 0; m1 <= 4 - m0; m1++) {
                    float v2 = v1;
                    #pragma unroll
                    for (int m2 = 0; m2 <= 4 - m0 - m1; m2++) {
                        float v3 = v2;
                        #pragma unroll
                        for (int m3 = 0; m3 <= 4 - m0 - m1 - m2; m3++) {
                            float v4 = v3;
                            #pragma unroll
                            for (int m4 = 0; m4 <= 4 - m0 - m1 - m2 - m3; m4++) {
                                if (r >= rlo && r < rhi) {
                                    g_phiT[(size_t)r * NPIX + n] = v4;
                                    float sv = v4;
                                    #pragma unroll
                                    for (int o2 = 16; o2 > 0; o2 >>= 1)
                                        sv += __shfl_xor_sync(0xffffffffu, sv, o2);
                                    if (lane == 0) atomicAdd(&g_M0[r], sv);
                                }
                                r++;
                                v4 *= f4 * (m4 == 0 ? S1 : m4 == 1 ? S2 : m4 == 2 ? S3 : S4);
                            }
                            v3 *= f3 * (m3 == 0 ? S1 : m3 == 1 ? S2 : m3 == 2 ? S3 : S4);
                        }
                        v2 *= f2 * (m2 == 0 ? S1 : m2 == 1 ? S2 : m2 == 2 ? S3 : S4);
                    }
                    v1 *= f1 * (m1 == 0 ? S1 : m1 == 1 ? S2 : m1 == 2 ? S3 : S4);
                }
                v0 *= f0 * (m0 == 0 ? S1 : m0 == 1 ? S2 : m0 == 2 ? S3 : S4);
            }
        }
    }
    // initial softmax (px per thread), writes linear + padded s
    if (bid < 288 && tid < PXB) {
        int n = bid * PXB + tid;
        int y = n / HW, x = n % HW;
        float q[NC];
        float m = -1e30f;
        #pragma unroll
        for (int c = 0; c < NC; c++) { q[c] = g_u[c * NPIX + n]; m = fmaxf(m, q[c]); }
        float ss = 0.0f;
        #pragma unroll
        for (int c = 0; c < NC; c++) { q[c] = expf(q[c] - m); ss += q[c]; }
        float inv = 1.0f / ss;
        #pragma unroll
        for (int c = 0; c < NC; c++) {
            float sv = q[c] * inv;
            g_s[c * NPIX + n] = sv;
            g_sP[c * HW * SPAD + y * SPAD + x + KR] = sv;
        }
    }
    gsync();

    // ======================= mean-field iterations ==========================
    for (int it = 0; it < 5; it++) {
        // ---- phase A: [it0: normbl], moments, spatial pass X ----
        if (it == 0) {
            for (int n = gtid; n < NPIX; n += NTHR) {
                float acc = 0.0f;
                for (int r = 0; r < RD; r++)
                    acc += g_phiT[(size_t)r * NPIX + n] * g_M0[r];
                g_normbl[n] = acc;
            }
        }
        {   // moments: block-task = (c, chunk); mom[c][r] += phi[r][*].s[c][*]
            float* sS = (float*)sraw;                    // 576 floats
            const ull* sS2 = (const ull*)sraw;
            int w = tid >> 5;
            for (int task = bid; task < MTASKS; task += GRID) {
                int c = task / NCHK, ch = task % NCHK;
                int n0 = ch * CHPX;
                __syncthreads();
                for (int i = tid; i < CHPX; i += TPB) sS[i] = g_s[c * NPIX + n0 + i];
                __syncthreads();
                for (int r = w; r < RD; r += 16) {
                    const ull* prow = (const ull*)g_phiT + (size_t)r * NPAIR + n0 / 2;
                    ull acc = 0ull;
                    #pragma unroll
                    for (int i = 0; i < 9; i++)
                        fma2(acc, prow[i * 32 + lane], sS2[i * 32 + lane]);
                    float v = __uint_as_float((unsigned)(acc & 0xffffffffull))
                            + __uint_as_float((unsigned)(acc >> 32));
                    #pragma unroll
                    for (int o2 = 16; o2 > 0; o2 >>= 1)
                        v += __shfl_xor_sync(0xffffffffu, v, o2);
                    if (lane == 0) atomicAdd(&g_mom[c * RD + r], v);
                }
            }
        }
        // spatial pass X on padded rows (no bounds checks)
        for (int o = gtid; o < NC * NPIX; o += NTHR) {
            int c = o / NPIX, rem = o % NPIX;
            int y = rem / HW, x = rem % HW;
            const float* srow = g_sP + c * HW * SPAD + y * SPAD + x;
            float acc = 0.0f;
            #pragma unroll
            for (int d = 0; d < KW; d++) acc += g_ker[d] * srow[d];
            g_tmpP[c * SPAD * HW + (y + KR) * HW + x] = acc;
        }
        gsync();

        // ---- phase B: spatial pass Y + normalize; bilateral backprojection --
        for (int o = gtid; o < NC * NPIX; o += NTHR) {
            int c = o / NPIX, rem = o % NPIX;
            int y = rem / HW, x = rem % HW;
            const float* tcol = g_tmpP + c * SPAD * HW + y * HW + x;
            float acc = 0.0f;
            #pragma unroll
            for (int d = 0; d < KW; d++) acc += g_ker[d] * tcol[d * HW];
            g_sp[o] = acc / (g_gsx[y] * g_gsx[x]);
        }
        {   // bl: warp-task = (c, 32-pair group): bl[c][n] = phi[:,n].mom[c]/normbl
            ull* sM2 = (ull*)sraw;                       // 2646 * 8 = 21168 B
            for (int i2 = tid; i2 < NC * RD; i2 += TPB) {
                unsigned ui = __float_as_uint(g_mom[i2]);
                sM2[i2] = ((ull)ui << 32) | (ull)ui;
            }
            __syncthreads();
            for (int wt = gwarp; wt < NC * (NPAIR / 32); wt += NTHR / 32) {
                int c = wt / (NPAIR / 32);
                int n2 = (wt % (NPAIR / 32)) * 32 + lane;
                const ull* mrow = sM2 + c * RD;
                ull acc = 0ull;
                #pragma unroll 7
                for (int r = 0; r < RD; r++)
                    fma2(acc, ((const ull*)g_phiT)[(size_t)r * NPAIR + n2], mrow[r]);
                ull nb = ((const ull*)g_normbl)[n2];
                float2 v;
                v.x = __uint_as_float((unsigned)(acc & 0xffffffffull))
                    / __uint_as_float((unsigned)(nb & 0xffffffffull));
                v.y = __uint_as_float((unsigned)(acc >> 32))
                    / __uint_as_float((unsigned)(nb >> 32));
                ((float2*)g_bl)[c * NPAIR + n2] = v;
            }
        }
        gsync();

        // ---- phase C: mixing + softmax; zero mom for next iter ----
        {
            float* sW1 = (float*)sraw;                   // 441
            float* sW2 = sW1 + NC * NC;                  // 441
            float* sCv = sW2 + NC * NC;                  // 21
            float* sBL = sCv + NC;                       // NC x 33
            float* sSP = sBL + NC * 33;                  // NC x 33
            float* sQ  = sSP + NC * 33;                  // NC x 33
            float* sIv = sQ  + NC * 33;                  // 32
            for (int i = tid; i < NC * NC; i += TPB) { sW1[i] = g_W1[i]; sW2[i] = g_W2[i]; }
            if (tid < NC) sCv[tid] = g_cvec[tid];
            for (int t = gtid; t < NC * RD; t += NTHR) g_mom[t] = 0.0f;

            int n0 = bid * PXB;
            bool act = (bid < 288);
            __syncthreads();
            if (act) {
                for (int t = tid; t < NC * PXB; t += TPB) {
                    int c = t / PXB, px = t % PXB;
                    sBL[c * 33 + px] = g_bl[c * NPIX + n0 + px];
                    sSP[c * 33 + px] = g_sp[c * NPIX + n0 + px];
                }
            }
            __syncthreads();
            if (act) {
                for (int t = tid; t < NC * PXB; t += TPB) {
                    int o = t / PXB, px = t % PXB;
                    float pair = sCv[o];
                    #pragma unroll
                    for (int c = 0; c < NC; c++)
                        pair += sW1[o * NC + c] * sSP[c * 33 + px]
                              + sW2[o * NC + c] * sBL[c * 33 + px];
                    sQ[o * 33 + px] = g_u[o * NPIX + n0 + px] - pair;
                }
            }
            __syncthreads();
            if (act && tid < PXB) {
                int px = tid;
                float m = -1e30f;
                #pragma unroll
                for (int o = 0; o < NC; o++) m = fmaxf(m, sQ[o * 33 + px]);
                float ssum = 0.0f;
                #pragma unroll
                for (int o = 0; o < NC; o++) {
                    float e = expf(sQ[o * 33 + px] - m);
                    sQ[o * 33 + px] = e;
                    ssum += e;
                }
                sIv[px] = 1.0f / ssum;
            }
            __syncthreads();
            if (act) {
                for (int t = tid; t < NC * PXB; t += TPB) {
                    int o = t / PXB, px = t % PXB;
                    int n = n0 + px;
                    float sv = sQ[o * 33 + px] * sIv[px];
                    g_s[o * NPIX + n] = sv;
                    int y = n / HW, x = n % HW;
                    g_sP[o * HW * SPAD + y * SPAD + x + KR] = sv;
                    if (it == 4) out[o * NPIX + n] = sv;
                }
            }
        }
        gsync();
    }
}

// ------------------------------ launch -------------------------------------
extern "C" void kernel_launch(void* const* d_in, const int* in_sizes, int n_in,
                              void* d_out, int out_size) {
    const float* image  = (const float*)d_in[0];
    const float* net_w  = (const float*)d_in[1];
    const float* net_b  = (const float*)d_in[2];
    const float* sp_w   = (const float*)d_in[3];
    const float* sp_b   = (const float*)d_in[4];
    const float* bl_w   = (const float*)d_in[5];
    const float* bl_b   = (const float*)d_in[6];
    const float* comp_w = (const float*)d_in[7];
    const float* comp_b = (const float*)d_in[8];
    float* out = (float*)d_out;

    crf_all<<<GRID, TPB>>>(image, net_w, net_b, sp_w, sp_b,
                           bl_w, bl_b, comp_w, comp_b, out);
}

// round 10
// speedup vs baseline: 2.5699x; 2.5699x over previous
#include <cuda_runtime.h>
#include <math.h>

// ---------------------------------------------------------------------------
// CRF-as-RNN forward — persistent kernel v5, owner-computes.
//  - 96 blocks x 1024 threads; block b owns image row y=b for the whole run
//  - per-block SMEM holds u, s, phi (deg-3 feature map, R=56) persistently
//  - per-iteration global exchange: x-filtered tmp (y-halo) + 21x56 moments
//  - ONE grid barrier per iteration (6 total)
// ---------------------------------------------------------------------------

typedef unsigned long long ull;

static constexpr int HW   = 96;
static constexpr int NPIX = HW * HW;
static constexpr int NC   = 21;
static constexpr int RD   = 56;             // monomials deg<=3 in 5 vars
static constexpr int GRID = 96;
static constexpr int TPB  = 1024;
static constexpr int NTHR = GRID * TPB;
static constexpr int KR   = 16;
static constexpr int KW   = 2 * KR + 1;     // 33
static constexpr int TROWS = HW + 2 * KR;   // 128 (y-padded tmp rows)
static constexpr int NMOM = NC * RD;        // 1176

// smem layout (float offsets)
static constexpr int O_M   = 0;             // 1176 ull  (2352 f)
static constexpr int O_K2  = 2352;          // 33 ull    (66 f)
static constexpr int O_PHI = 2418;          // 56 x 98
static constexpr int O_S   = 7906;          // 21 x 128 (x-padded, +16 offset)
static constexpr int O_U   = 10594;         // 21 x 96
static constexpr int O_SP  = 12610;         // 21 x 96
static constexpr int O_BL  = 14626;         // 21 x 96
static constexpr int O_Q   = 16642;         // 21 x 96
static constexpr int O_NBI = 18658;         // 96
static constexpr int O_GIX = 18754;         // 96
static constexpr int O_KER = 18850;         // 33 (+pad)
static constexpr int SMEM_BYTES = 18884 * 4;

// ------------------------- device scratch ----------------------------------
__device__ __align__(16) float g_tmpP[NC * TROWS * HW];  // y-padded tmp
__device__ float g_mom[3 * NMOM];           // triple-buffered moments
__device__ float g_M0[RD];
__device__ float g_ker[KW];
__device__ float g_gsx[HW];
__device__ float g_W1[NC * NC], g_W2[NC * NC], g_cvec[NC];
__device__ unsigned g_barCount = 0, g_barGen = 0;

// CG-style grid barrier (96 blocks, 1/SM, all resident)
__device__ __forceinline__ void gsync() {
    __syncthreads();
    if (threadIdx.x == 0) {
        unsigned* cnt = &g_barCount;
        unsigned* gen = &g_barGen;
        unsigned my;
        asm volatile("ld.relaxed.gpu.u32 %0, [%1];" : "=r"(my) : "l"(gen));
        unsigned prev;
        asm volatile("atom.add.release.gpu.u32 %0, [%1], 1;"
                     : "=r"(prev) : "l"(cnt) : "memory");
        if (prev == GRID - 1u) {
            asm volatile("st.relaxed.gpu.u32 [%0], %1;" :: "l"(cnt), "r"(0u));
            asm volatile("st.release.gpu.u32 [%0], %1;"
                         :: "l"(gen), "r"(my + 1u) : "memory");
        } else {
            unsigned cur;
            do {
                __nanosleep(32);
                asm volatile("ld.acquire.gpu.u32 %0, [%1];"
                             : "=r"(cur) : "l"(gen) : "memory");
            } while (cur == my);
        }
    }
    __syncthreads();
}

__device__ __forceinline__ void fma2(ull& acc, ull a, ull b) {
    asm("fma.rn.f32x2 %0, %1, %2, %0;" : "+l"(acc) : "l"(a), "l"(b));
}
__device__ __forceinline__ ull dup2(float v) {
    unsigned u = __float_as_uint(v);
    return ((ull)u << 32) | (ull)u;
}
__device__ __forceinline__ float lo2(ull a) { return __uint_as_float((unsigned)a); }
__device__ __forceinline__ float hi2(ull a) { return __uint_as_float((unsigned)(a >> 32)); }

__global__ __launch_bounds__(TPB, 1) void crf_all(
    const float* __restrict__ img,
    const float* __restrict__ net_w, const float* __restrict__ net_b,
    const float* __restrict__ sp_w,  const float* __restrict__ sp_b,
    const float* __restrict__ bl_w,  const float* __restrict__ bl_b,
    const float* __restrict__ comp_w,const float* __restrict__ comp_b,
    float* __restrict__ out)
{
    extern __shared__ float sm[];
    ull*   sM   = (ull*)sm;
    ull*   sK2  = (ull*)(sm + O_K2);
    float* sPhi = sm + O_PHI;
    float* sS   = sm + O_S;
    float* sU   = sm + O_U;
    float* sSp  = sm + O_SP;
    float* sBl  = sm + O_BL;
    float* sQ   = sm + O_Q;
    float* sNbI = sm + O_NBI;
    float* sGix = sm + O_GIX;
    float* sKer = sm + O_KER;

    const int tid  = threadIdx.x;
    const int bid  = blockIdx.x;
    const int gtid = bid * TPB + tid;
    const int y    = bid;                    // owned image row

    // ======================= P0: setup ======================================
    for (int t = gtid; t < 3 * NMOM; t += NTHR) g_mom[t] = 0.0f;
    for (int t = gtid; t < RD; t += NTHR) g_M0[t] = 0.0f;
    for (int t = gtid; t < KW; t += NTHR) {
        float d = (float)(t - KR) * (1.0f / 3.0f);
        g_ker[t] = expf(-0.5f * d * d);
    }
    for (int t = gtid; t < HW; t += NTHR) {
        float acc = 0.0f;
        for (int d = 0; d < KW; d++) {
            int xx = t + d - KR;
            if (xx >= 0 && xx < HW) {
                float dd = (float)(d - KR) * (1.0f / 3.0f);
                acc += expf(-0.5f * dd * dd);
            }
        }
        g_gsx[t] = acc;
    }
    for (int t = gtid; t < NC * NC; t += NTHR) {
        int o = t / NC, k = t % NC;
        float a1 = 0.0f, a2 = 0.0f;
        for (int c = 0; c < NC; c++) {
            a1 += comp_w[o * NC + c] * sp_w[c * NC + k];
            a2 += comp_w[o * NC + c] * bl_w[c * NC + k];
        }
        g_W1[t] = a1; g_W2[t] = a2;
    }
    for (int t = gtid; t < NC; t += NTHR) {
        float cv = comp_b[t];
        for (int c = 0; c < NC; c++) cv += comp_w[t * NC + c] * (sp_b[c] + bl_b[c]);
        g_cvec[t] = cv;
    }
    // zero tmpP y-border rows (0..15 and 112..127)
    for (int t = gtid; t < NC * 2 * KR * HW; t += NTHR) {
        int c = t / (2 * KR * HW), rem = t % (2 * KR * HW);
        int r = rem / HW, x = rem % HW;
        int row = (r < KR) ? r : (TROWS - 2 * KR + r);
        g_tmpP[(c * TROWS + row) * HW + x] = 0.0f;
    }
    // unary 3x3 conv for own row -> sU (block-local)
    for (int t = tid; t < NC * HW; t += TPB) {
        int o = t / HW, x = t % HW;
        float acc = __ldg(&net_b[o]);
        #pragma unroll
        for (int c = 0; c < 3; c++)
            #pragma unroll
            for (int ky = 0; ky < 3; ky++) {
                int yy = y + ky - 1;
                if (yy < 0 || yy >= HW) continue;
                #pragma unroll
                for (int kx = 0; kx < 3; kx++) {
                    int xx = x + kx - 1;
                    if (xx < 0 || xx >= HW) continue;
                    acc += img[c * NPIX + yy * HW + xx]
                         * __ldg(&net_w[((o * 3 + c) * 3 + ky) * 3 + kx]);
                }
            }
        sU[o * 96 + x] = acc;
    }
    // zero sS x-pads
    for (int t = tid; t < NC * 2 * KR; t += TPB) {
        int c = t / (2 * KR), j = t % (2 * KR);
        sS[c * 128 + (j < KR ? j : 96 + j)] = 0.0f;
    }
    gsync();

    // ======================= P1: phi, M0, softmax0, tmp0, mom0 ==============
    if (tid < HW) {                          // build phi for own pixel
        int px = tid;
        float f0 = ((float)px - 47.5f) * (1.0f / 160.0f);
        float f1 = ((float)y  - 47.5f) * (1.0f / 160.0f);
        int n = y * HW + px;
        float f2 = (img[0 * NPIX + n] - 0.5f) * (1.0f / 3.0f);
        float f3 = (img[1 * NPIX + n] - 0.5f) * (1.0f / 3.0f);
        float f4 = (img[2 * NPIX + n] - 0.5f) * (1.0f / 3.0f);
        float a = expf(-0.5f * (f0*f0 + f1*f1 + f2*f2 + f3*f3 + f4*f4));
        const float I2 = 0.70710678f, I3 = 0.57735027f;
        int r = 0;
        float v0 = a;
        for (int m0 = 0; m0 <= 3; m0++) {
            float v1 = v0;
            for (int m1 = 0; m1 <= 3 - m0; m1++) {
                float v2 = v1;
                for (int m2 = 0; m2 <= 3 - m0 - m1; m2++) {
                    float v3 = v2;
                    for (int m3 = 0; m3 <= 3 - m0 - m1 - m2; m3++) {
                        float v4 = v3;
                        for (int m4 = 0; m4 <= 3 - m0 - m1 - m2 - m3; m4++) {
                            sPhi[r * 98 + px] = v4;
                            r++;
                            v4 *= f4 * (m4 == 0 ? 1.0f : m4 == 1 ? I2 : I3);
                        }
                        v3 *= f3 * (m3 == 0 ? 1.0f : m3 == 1 ? I2 : I3);
                    }
                    v2 *= f2 * (m2 == 0 ? 1.0f : m2 == 1 ? I2 : I3);
                }
                v1 *= f1 * (m1 == 0 ? 1.0f : m1 == 1 ? I2 : I3);
            }
            v0 *= f0 * (m0 == 0 ? 1.0f : m0 == 1 ? I2 : I3);
        }
    }
    if (tid >= 128 && tid < 128 + KW) {
        int d = tid - 128;
        float k = g_ker[d];
        sKer[d] = k;
        sK2[d] = dup2(k);
    }
    if (tid >= 192 && tid < 192 + HW) {
        int x = tid - 192;
        sGix[x] = 1.0f / (g_gsx[y] * g_gsx[x]);
    }
    __syncthreads();
    if (tid < RD) {                          // M0 partial
        float acc = 0.0f;
        for (int px = 0; px < HW; px++) acc += sPhi[tid * 98 + px];
        atomicAdd(&g_M0[tid], acc);
    }
    if (tid >= 64 && tid < 64 + HW) {        // softmax0
        int px = tid - 64;
        float m = -1e30f;
        #pragma unroll
        for (int o = 0; o < NC; o++) m = fmaxf(m, sU[o * 96 + px]);
        float ss = 0.0f;
        float e[NC];
        #pragma unroll
        for (int o = 0; o < NC; o++) { e[o] = expf(sU[o * 96 + px] - m); ss += e[o]; }
        float inv = 1.0f / ss;
        #pragma unroll
        for (int o = 0; o < NC; o++) sS[o * 128 + KR + px] = e[o] * inv;
    }
    __syncthreads();
    // mom_0 (buffer 0) + tmp_0
    if (tid < 98) {
        int rg = tid % 14, cg = tid / 14;
        int r0 = rg * 4, c0 = cg * 3;
        ull acc[12];
        #pragma unroll
        for (int k = 0; k < 12; k++) acc[k] = 0ull;
        for (int p = 0; p < 48; p++) {
            ull ph0 = *(const ull*)(sPhi + (r0 + 0) * 98 + 2 * p);
            ull ph1 = *(const ull*)(sPhi + (r0 + 1) * 98 + 2 * p);
            ull ph2 = *(const ull*)(sPhi + (r0 + 2) * 98 + 2 * p);
            ull ph3 = *(const ull*)(sPhi + (r0 + 3) * 98 + 2 * p);
            #pragma unroll
            for (int j = 0; j < 3; j++) {
                ull sv = *(const ull*)(sS + (c0 + j) * 128 + KR + 2 * p);
                fma2(acc[j * 4 + 0], ph0, sv);
                fma2(acc[j * 4 + 1], ph1, sv);
                fma2(acc[j * 4 + 2], ph2, sv);
                fma2(acc[j * 4 + 3], ph3, sv);
            }
        }
        #pragma unroll
        for (int j = 0; j < 3; j++)
            #pragma unroll
            for (int i = 0; i < 4; i++)
                atomicAdd(&g_mom[0 * NMOM + (c0 + j) * RD + r0 + i],
                          lo2(acc[j * 4 + i]) + hi2(acc[j * 4 + i]));
    }
    if (tid >= 128) {
        for (int t = tid - 128; t < NC * HW; t += TPB - 128) {
            int c = t / HW, x = t % HW;
            const float* sr = sS + c * 128 + x;
            float acc = 0.0f;
            #pragma unroll
            for (int d = 0; d < KW; d++) acc += sKer[d] * sr[d];
            g_tmpP[(c * TROWS + y + KR) * HW + x] = acc;
        }
    }
    gsync();

    // ======================= mean-field iterations ==========================
    for (int it = 0; it < 5; it++) {
        int rdb = it % 3, wrb = (it + 1) % 3, zrb = (it + 2) % 3;
        // ---- stage 1: normbl (it0), load moments, zero future buffer ----
        if (it == 0 && tid < HW) {
            int px = tid;
            float acc = 0.0f;
            for (int r = 0; r < RD; r++) acc += sPhi[r * 98 + px] * g_M0[r];
            sNbI[px] = 1.0f / acc;
        }
        for (int t = tid; t < NMOM; t += TPB) sM[t] = dup2(g_mom[rdb * NMOM + t]);
        if (it < 4)
            for (int t = tid; t < NMOM; t += TPB) g_mom[zrb * NMOM + t] = 0.0f;
        __syncthreads();

        // ---- stage 2: bl (threads 0..335) + spY (336..1023) ----
        if (tid < 336) {
            int pr = tid % 48, cg = tid / 48;
            int c0 = cg * 3;
            ull a0 = 0ull, a1 = 0ull, a2 = 0ull;
            for (int r = 0; r < RD; r++) {
                ull ph = *(const ull*)(sPhi + r * 98 + 2 * pr);
                fma2(a0, ph, sM[(c0 + 0) * RD + r]);
                fma2(a1, ph, sM[(c0 + 1) * RD + r]);
                fma2(a2, ph, sM[(c0 + 2) * RD + r]);
            }
            float i0 = sNbI[2 * pr], i1 = sNbI[2 * pr + 1];
            sBl[(c0 + 0) * 96 + 2 * pr] = lo2(a0) * i0;
            sBl[(c0 + 0) * 96 + 2 * pr + 1] = hi2(a0) * i1;
            sBl[(c0 + 1) * 96 + 2 * pr] = lo2(a1) * i0;
            sBl[(c0 + 1) * 96 + 2 * pr + 1] = hi2(a1) * i1;
            sBl[(c0 + 2) * 96 + 2 * pr] = lo2(a2) * i0;
            sBl[(c0 + 2) * 96 + 2 * pr + 1] = hi2(a2) * i1;
        } else {
            for (int t = tid - 336; t < NC * 48; t += TPB - 336) {
                int c = t / 48, pr = t % 48;
                ull acc = 0ull;
                const float* base = g_tmpP + (c * TROWS + y) * HW + 2 * pr;
                #pragma unroll
                for (int d = 0; d < KW; d++)
                    fma2(acc, *(const ull*)(base + d * HW), sK2[d]);
                sSp[c * 96 + 2 * pr] = lo2(acc) * sGix[2 * pr];
                sSp[c * 96 + 2 * pr + 1] = hi2(acc) * sGix[2 * pr + 1];
            }
        }
        __syncthreads();

        // ---- stage 3: mixing ----
        if (tid < 672) {
            int px = tid % 96, og = tid / 96;
            int o0 = og * 3;
            float q0 = __ldg(&g_cvec[o0 + 0]);
            float q1 = __ldg(&g_cvec[o0 + 1]);
            float q2 = __ldg(&g_cvec[o0 + 2]);
            for (int c = 0; c < NC; c++) {
                float sp = sSp[c * 96 + px], bl = sBl[c * 96 + px];
                q0 += __ldg(&g_W1[(o0 + 0) * NC + c]) * sp + __ldg(&g_W2[(o0 + 0) * NC + c]) * bl;
                q1 += __ldg(&g_W1[(o0 + 1) * NC + c]) * sp + __ldg(&g_W2[(o0 + 1) * NC + c]) * bl;
                q2 += __ldg(&g_W1[(o0 + 2) * NC + c]) * sp + __ldg(&g_W2[(o0 + 2) * NC + c]) * bl;
            }
            sQ[(o0 + 0) * 96 + px] = sU[(o0 + 0) * 96 + px] - q0;
            sQ[(o0 + 1) * 96 + px] = sU[(o0 + 1) * 96 + px] - q1;
            sQ[(o0 + 2) * 96 + px] = sU[(o0 + 2) * 96 + px] - q2;
        }
        __syncthreads();

        // ---- stage 4: softmax (+ output on final iteration) ----
        if (tid < HW) {
            int px = tid;
            float m = -1e30f;
            #pragma unroll
            for (int o = 0; o < NC; o++) m = fmaxf(m, sQ[o * 96 + px]);
            float ss = 0.0f;
            #pragma unroll
            for (int o = 0; o < NC; o++) {
                float e = expf(sQ[o * 96 + px] - m);
                sQ[o * 96 + px] = e;
                ss += e;
            }
            float inv = 1.0f / ss;
            #pragma unroll
            for (int o = 0; o < NC; o++) {
                float sv = sQ[o * 96 + px] * inv;
                sS[o * 128 + KR + px] = sv;
                if (it == 4) out[o * NPIX + y * HW + px] = sv;
            }
        }
        if (it == 4) break;
        __syncthreads();

        // ---- stage 5: next-iteration moments + spX ----
        if (tid < 98) {
            int rg = tid % 14, cg = tid / 14;
            int r0 = rg * 4, c0 = cg * 3;
            ull acc[12];
            #pragma unroll
            for (int k = 0; k < 12; k++) acc[k] = 0ull;
            for (int p = 0; p < 48; p++) {
                ull ph0 = *(const ull*)(sPhi + (r0 + 0) * 98 + 2 * p);
                ull ph1 = *(const ull*)(sPhi + (r0 + 1) * 98 + 2 * p);
                ull ph2 = *(const ull*)(sPhi + (r0 + 2) * 98 + 2 * p);
                ull ph3 = *(const ull*)(sPhi + (r0 + 3) * 98 + 2 * p);
                #pragma unroll
                for (int j = 0; j < 3; j++) {
                    ull sv = *(const ull*)(sS + (c0 + j) * 128 + KR + 2 * p);
                    fma2(acc[j * 4 + 0], ph0, sv);
                    fma2(acc[j * 4 + 1], ph1, sv);
                    fma2(acc[j * 4 + 2], ph2, sv);
                    fma2(acc[j * 4 + 3], ph3, sv);
                }
            }
            #pragma unroll
            for (int j = 0; j < 3; j++)
                #pragma unroll
                for (int i = 0; i < 4; i++)
                    atomicAdd(&g_mom[wrb * NMOM + (c0 + j) * RD + r0 + i],
                              lo2(acc[j * 4 + i]) + hi2(acc[j * 4 + i]));
        }
        if (tid >= 128) {
            for (int t = tid - 128; t < NC * HW; t += TPB - 128) {
                int c = t / HW, x = t % HW;
                const float* sr = sS + c * 128 + x;
                float acc = 0.0f;
                #pragma unroll
                for (int d = 0; d < KW; d++) acc += sKer[d] * sr[d];
                g_tmpP[(c * TROWS + y + KR) * HW + x] = acc;
            }
        }
        gsync();
    }
}

// ------------------------------ launch -------------------------------------
extern "C" void kernel_launch(void* const* d_in, const int* in_sizes, int n_in,
                              void* d_out, int out_size) {
    const float* image  = (const float*)d_in[0];
    const float* net_w  = (const float*)d_in[1];
    const float* net_b  = (const float*)d_in[2];
    const float* sp_w   = (const float*)d_in[3];
    const float* sp_b   = (const float*)d_in[4];
    const float* bl_w   = (const float*)d_in[5];
    const float* bl_b   = (const float*)d_in[6];
    const float* comp_w = (const float*)d_in[7];
    const float* comp_b = (const float*)d_in[8];
    float* out = (float*)d_out;

    static int smem_set = 0;
    if (!smem_set) {
        cudaFuncSetAttribute(crf_all, cudaFuncAttributeMaxDynamicSharedMemorySize,
                             SMEM_BYTES);
        smem_set = 1;
    }
    crf_all<<<GRID, TPB, SMEM_BYTES>>>(image, net_w, net_b, sp_w, sp_b,
                                       bl_w, bl_b, comp_w, comp_b, out);
}

// round 11
// speedup vs baseline: 3.1948x; 1.2432x over previous
#include <cuda_runtime.h>
#include <math.h>

// ---------------------------------------------------------------------------
// CRF-as-RNN forward — persistent kernel v6, owner-computes.
//  - 96 blocks x 1024 threads; block b owns image row y=b
//  - per-block SMEM holds img window, u, s, phi (deg-3, R=56) persistently
//  - per-iteration global exchange: x-filtered tmp (y-halo) + 21x56 moments
//  - 5 grid barriers total (1 setup + 4 iteration)
//  - zero-invariants self-sustaining across launches (graph replays)
// ---------------------------------------------------------------------------

typedef unsigned long long ull;

static constexpr int HW   = 96;
static constexpr int NPIX = HW * HW;
static constexpr int NC   = 21;
static constexpr int RD   = 56;             // monomials deg<=3 in 5 vars
static constexpr int GRID = 96;
static constexpr int TPB  = 1024;
static constexpr int NTHR = GRID * TPB;
static constexpr int KR   = 16;
static constexpr int KW   = 2 * KR + 1;     // 33
static constexpr int TROWS = HW + 2 * KR;   // 128
static constexpr int NMOM = NC * RD;        // 1176
static constexpr int PHS  = 104;            // sPhi row stride (16B-aligned)

// smem offsets (floats) — all 16B aligned
static constexpr int O_MF   = 0;                    // 1176
static constexpr int O_MOMP = O_MF + NMOM;          // 4*1176
static constexpr int O_PHI  = O_MOMP + 4 * NMOM;    // 56*104
static constexpr int O_S    = O_PHI + RD * PHS;     // 21*128 (x-padded, +16)
static constexpr int O_U    = O_S + NC * 128;       // 21*96
static constexpr int O_SP   = O_U + NC * 96;
static constexpr int O_BL   = O_SP + NC * 96;
static constexpr int O_Q    = O_BL + NC * 96;
static constexpr int O_W1   = O_Q + NC * 96;        // 444
static constexpr int O_W2   = O_W1 + 444;
static constexpr int O_CV   = O_W2 + 444;           // 24
static constexpr int O_KER  = O_CV + 24;            // 36
static constexpr int O_GSX  = O_KER + 36;           // 96
static constexpr int O_GIX  = O_GSX + 96;           // 96
static constexpr int O_NBI  = O_GIX + 96;           // 96
static constexpr int O_IMG  = O_NBI + 96;           // 3*3*96
static constexpr int O_NW   = O_IMG + 864;          // 568
static constexpr int O_NB   = O_NW + 568;           // 28
static constexpr int SMEMF  = O_NB + 28;
static constexpr int SMEM_BYTES = SMEMF * 4;        // ~100.6 KB

// ------------------------- device scratch ----------------------------------
// g_tmpP borders (rows 0..15, 112..127) are zero-initialized at module load
// and NEVER written — spX only writes rows 16..111. Persistent across launches.
__device__ __align__(16) float g_tmpP[NC * TROWS * HW];
__device__ float g_mom[3 * NMOM];           // triple-buffered; zero-invariant
__device__ float g_M0[RD];                  // zero-invariant
__device__ unsigned g_barCount = 0, g_barGen = 0;

// CG-style grid barrier (96 blocks, 1/SM, all resident)
__device__ __forceinline__ void gsync() {
    __syncthreads();
    if (threadIdx.x == 0) {
        unsigned* cnt = &g_barCount;
        unsigned* gen = &g_barGen;
        unsigned my;
        asm volatile("ld.relaxed.gpu.u32 %0, [%1];" : "=r"(my) : "l"(gen));
        unsigned prev;
        asm volatile("atom.add.release.gpu.u32 %0, [%1], 1;"
                     : "=r"(prev) : "l"(cnt) : "memory");
        if (prev == GRID - 1u) {
            asm volatile("st.relaxed.gpu.u32 [%0], %1;" :: "l"(cnt), "r"(0u));
            asm volatile("st.release.gpu.u32 [%0], %1;"
                         :: "l"(gen), "r"(my + 1u) : "memory");
        } else {
            unsigned cur;
            do {
                __nanosleep(32);
                asm volatile("ld.acquire.gpu.u32 %0, [%1];"
                             : "=r"(cur) : "l"(gen) : "memory");
            } while (cur == my);
        }
    }
    __syncthreads();
}

__device__ __forceinline__ void fma2(ull& acc, ull a, ull b) {
    asm("fma.rn.f32x2 %0, %1, %2, %0;" : "+l"(acc) : "l"(a), "l"(b));
}
__device__ __forceinline__ float lo2(ull a) { return __uint_as_float((unsigned)a); }
__device__ __forceinline__ float hi2(ull a) { return __uint_as_float((unsigned)(a >> 32)); }

__global__ __launch_bounds__(TPB, 1) void crf_all(
    const float* __restrict__ img,
    const float* __restrict__ net_w, const float* __restrict__ net_b,
    const float* __restrict__ sp_w,  const float* __restrict__ sp_b,
    const float* __restrict__ bl_w,  const float* __restrict__ bl_b,
    const float* __restrict__ comp_w,const float* __restrict__ comp_b,
    float* __restrict__ out)
{
    extern __shared__ float sm[];
    float* sMf   = sm + O_MF;
    float* sMomP = sm + O_MOMP;
    float* sPhi  = sm + O_PHI;
    float* sS    = sm + O_S;      // stride 128, data at +16
    float* sU    = sm + O_U;
    float* sSp   = sm + O_SP;
    float* sBl   = sm + O_BL;
    float* sQ    = sm + O_Q;
    float* sW1   = sm + O_W1;
    float* sW2   = sm + O_W2;
    float* sCv   = sm + O_CV;
    float* sKer  = sm + O_KER;
    float* sGsx  = sm + O_GSX;
    float* sGix  = sm + O_GIX;
    float* sNbI  = sm + O_NBI;
    float* sImg  = sm + O_IMG;    // [c][row 0..2][96]
    float* sNw   = sm + O_NW;
    float* sNb   = sm + O_NB;

    const int tid  = threadIdx.x;
    const int y    = blockIdx.x;             // owned image row
    const int gtid = y * TPB + tid;

    // =================== setup (a): loads + global zeroing ==================
    // zero mom buffers 1 and 2 (pre-barrier; only buffer 0 gets setup atomics)
    for (int t = gtid; t < 2 * NMOM; t += NTHR) g_mom[NMOM + t] = 0.0f;
    for (int t = tid; t < KW; t += TPB) {
        float d = (float)(t - KR) * (1.0f / 3.0f);
        sKer[t] = expf(-0.5f * d * d);
    }
    for (int t = tid; t < 567; t += TPB) sNw[t] = net_w[t];
    for (int t = tid; t < NC; t += TPB) sNb[t] = net_b[t];
    for (int t = tid; t < 3 * 3 * HW; t += TPB) {
        int c = t / 288, rem = t % 288;
        int ry = rem / 96, x = rem % 96;
        int yy = y + ry - 1;
        sImg[t] = (yy >= 0 && yy < HW) ? img[c * NPIX + yy * HW + x] : 0.0f;
    }
    for (int t = tid; t < NC * NC; t += TPB) {
        int o = t / NC, k = t % NC;
        float a1 = 0.0f, a2 = 0.0f;
        for (int c = 0; c < NC; c++) {
            a1 += comp_w[o * NC + c] * sp_w[c * NC + k];
            a2 += comp_w[o * NC + c] * bl_w[c * NC + k];
        }
        sW1[o * NC + k] = a1;
        sW2[o * NC + k] = a2;
    }
    for (int t = tid; t < NC; t += TPB) {
        float cv = comp_b[t];
        for (int c = 0; c < NC; c++) cv += comp_w[t * NC + c] * (sp_b[c] + bl_b[c]);
        sCv[t] = cv;
    }
    __syncthreads();

    // =================== setup (b): gsx + phi | unary =======================
    if (tid < HW) {
        int px = tid;
        float acc = 0.0f;
        #pragma unroll
        for (int d = 0; d < KW; d++) {
            int xx = px + d - KR;
            if (xx >= 0 && xx < HW) acc += sKer[d];
        }
        sGsx[px] = acc;
        // phi (deg-3 feature map) from smem img center row
        float f0 = ((float)px - 47.5f) * (1.0f / 160.0f);
        float f1 = ((float)y  - 47.5f) * (1.0f / 160.0f);
        float f2 = (sImg[0 * 288 + 96 + px] - 0.5f) * (1.0f / 3.0f);
        float f3 = (sImg[1 * 288 + 96 + px] - 0.5f) * (1.0f / 3.0f);
        float f4 = (sImg[2 * 288 + 96 + px] - 0.5f) * (1.0f / 3.0f);
        float a = expf(-0.5f * (f0*f0 + f1*f1 + f2*f2 + f3*f3 + f4*f4));
        const float I2 = 0.70710678f, I3 = 0.57735027f;
        int r = 0;
        float v0 = a;
        for (int m0 = 0; m0 <= 3; m0++) {
            float v1 = v0;
            for (int m1 = 0; m1 <= 3 - m0; m1++) {
                float v2 = v1;
                for (int m2 = 0; m2 <= 3 - m0 - m1; m2++) {
                    float v3 = v2;
                    for (int m3 = 0; m3 <= 3 - m0 - m1 - m2; m3++) {
                        float v4 = v3;
                        for (int m4 = 0; m4 <= 3 - m0 - m1 - m2 - m3; m4++) {
                            sPhi[r * PHS + px] = v4;
                            r++;
                            v4 *= f4 * (m4 == 0 ? 1.0f : m4 == 1 ? I2 : I3);
                        }
                        v3 *= f3 * (m3 == 0 ? 1.0f : m3 == 1 ? I2 : I3);
                    }
                    v2 *= f2 * (m2 == 0 ? 1.0f : m2 == 1 ? I2 : I3);
                }
                v1 *= f1 * (m1 == 0 ? 1.0f : m1 == 1 ? I2 : I3);
            }
            v0 *= f0 * (m0 == 0 ? 1.0f : m0 == 1 ? I2 : I3);
        }
    } else {
        // unary 3x3 conv from smem
        for (int t = tid - 96; t < NC * HW; t += TPB - 96) {
            int o = t / HW, x = t % HW;
            float acc = sNb[o];
            #pragma unroll
            for (int c = 0; c < 3; c++)
                #pragma unroll
                for (int ky = 0; ky < 3; ky++)
                    #pragma unroll
                    for (int kx = 0; kx < 3; kx++) {
                        int xx = x + kx - 1;
                        if (xx < 0 || xx >= HW) continue;
                        acc += sImg[c * 288 + ky * 96 + xx]
                             * sNw[((o * 3 + c) * 3 + ky) * 3 + kx];
                    }
            sU[t] = acc;
        }
    }
    __syncthreads();

    // ============ setup (c): gix | softmax-exp | M0 atomics =================
    if (tid < HW) {
        sGix[tid] = 1.0f / (sGsx[y] * sGsx[tid]);
    } else if (tid < 768) {
        for (int u = tid - 96; u < NC * HW; u += 672) sQ[u] = expf(sU[u]);
    } else if (tid < 768 + RD) {
        int r = tid - 768;
        float acc = 0.0f;
        for (int px = 0; px < HW; px++) acc += sPhi[r * PHS + px];
        atomicAdd(&g_M0[r], acc);        // zeroed by previous launch (it==2)
    }
    __syncthreads();

    // ============ setup (d): softmax-normalize | sS x-pads ==================
    if (tid < HW) {
        int px = tid;
        float ss = 0.0f;
        #pragma unroll
        for (int o = 0; o < NC; o++) ss += sQ[o * 96 + px];
        float inv = 1.0f / ss;
        #pragma unroll
        for (int o = 0; o < NC; o++) sS[o * 128 + 16 + px] = sQ[o * 96 + px] * inv;
    } else {
        for (int t = tid - 96; t < NC * 2 * KR; t += TPB - 96) {
            int c = t / 32, j = t % 32;
            sS[c * 128 + (j < 16 ? j : 96 + j)] = 0.0f;
        }
    }
    __syncthreads();

    // ============ setup (e): mom0 partials | tmp0 (spX) =====================
    if (tid < 392) {
        int quarter = tid / 98, r2 = tid % 98;
        int cg = r2 / 14, rg = r2 % 14;
        int r0 = rg * 4, c0 = cg * 3;
        ull acc[12];
        #pragma unroll
        for (int k = 0; k < 12; k++) acc[k] = 0ull;
        int p0 = quarter * 12;
        for (int p = p0; p < p0 + 12; p++) {
            ull ph0 = *(const ull*)(sPhi + (r0 + 0) * PHS + 2 * p);
            ull ph1 = *(const ull*)(sPhi + (r0 + 1) * PHS + 2 * p);
            ull ph2 = *(const ull*)(sPhi + (r0 + 2) * PHS + 2 * p);
            ull ph3 = *(const ull*)(sPhi + (r0 + 3) * PHS + 2 * p);
            #pragma unroll
            for (int j = 0; j < 3; j++) {
                ull sv = *(const ull*)(sS + (c0 + j) * 128 + 16 + 2 * p);
                fma2(acc[j * 4 + 0], ph0, sv);
                fma2(acc[j * 4 + 1], ph1, sv);
                fma2(acc[j * 4 + 2], ph2, sv);
                fma2(acc[j * 4 + 3], ph3, sv);
            }
        }
        #pragma unroll
        for (int j = 0; j < 3; j++)
            #pragma unroll
            for (int i = 0; i < 4; i++)
                sMomP[quarter * NMOM + (c0 + j) * RD + r0 + i] =
                    lo2(acc[j * 4 + i]) + hi2(acc[j * 4 + i]);
    } else {
        for (int t = tid - 392; t < NC * HW; t += TPB - 392) {
            int c = t / HW, x = t % HW;
            const float* sr = sS + c * 128 + x;
            float acc = 0.0f;
            #pragma unroll
            for (int d = 0; d < KW; d++) acc += sKer[d] * sr[d];
            g_tmpP[(c * TROWS + KR + y) * HW + x] = acc;
        }
    }
    __syncthreads();
    // setup (f): reduce partials -> mom buffer 0 (zeroed by prev launch it==4)
    for (int t = tid; t < NMOM; t += TPB) {
        float v = sMomP[t] + sMomP[NMOM + t] + sMomP[2 * NMOM + t] + sMomP[3 * NMOM + t];
        atomicAdd(&g_mom[t], v);
    }
    gsync();                                 // barrier #1

    // ======================= mean-field iterations ==========================
    for (int it = 0; it < 5; it++) {
        const int rdb = it % 3, wrb = (it + 1) % 3, zrb = (it + 2) % 3;

        // ---- stage 1: load moments, zero future buffer, [it0: normbl] ------
        for (int t = tid; t < NMOM; t += TPB) sMf[t] = g_mom[rdb * NMOM + t];
        for (int t = tid; t < NMOM; t += TPB) g_mom[zrb * NMOM + t] = 0.0f;
        if (it == 0 && tid < HW) {
            int px = tid;
            float acc = 0.0f;
            for (int r = 0; r < RD; r++) acc += sPhi[r * PHS + px] * g_M0[r];
            sNbI[px] = 1.0f / acc;
        }
        if (it == 2 && tid >= 128 && tid < 128 + RD) g_M0[tid - 128] = 0.0f;
        __syncthreads();

        // ---- stage 2: bl (0..503) | spY (512..1015) ------------------------
        if (tid < 504) {
            int c = tid / 24, q = tid % 24;
            float4 a = make_float4(0.f, 0.f, 0.f, 0.f);
            const float* mrow = sMf + c * RD;
            #pragma unroll 8
            for (int r = 0; r < RD; r++) {
                float4 ph = *(const float4*)(sPhi + r * PHS + 4 * q);
                float m = mrow[r];
                a.x += ph.x * m; a.y += ph.y * m;
                a.z += ph.z * m; a.w += ph.w * m;
            }
            int px = 4 * q;
            sBl[c * 96 + px + 0] = a.x * sNbI[px + 0];
            sBl[c * 96 + px + 1] = a.y * sNbI[px + 1];
            sBl[c * 96 + px + 2] = a.z * sNbI[px + 2];
            sBl[c * 96 + px + 3] = a.w * sNbI[px + 3];
        } else if (tid >= 512 && tid < 1016) {
            int u = tid - 512;
            int c = u / 24, q = u % 24;
            float4 a = make_float4(0.f, 0.f, 0.f, 0.f);
            const float* base = g_tmpP + (c * TROWS + y) * HW + 4 * q;
            #pragma unroll
            for (int d = 0; d < KW; d++) {
                float4 tv = *(const float4*)(base + d * HW);
                float k = sKer[d];
                a.x += tv.x * k; a.y += tv.y * k;
                a.z += tv.z * k; a.w += tv.w * k;
            }
            int px = 4 * q;
            sSp[c * 96 + px + 0] = a.x * sGix[px + 0];
            sSp[c * 96 + px + 1] = a.y * sGix[px + 1];
            sSp[c * 96 + px + 2] = a.z * sGix[px + 2];
            sSp[c * 96 + px + 3] = a.w * sGix[px + 3];
        }
        __syncthreads();

        // ---- stage 3: mixing + exp -----------------------------------------
        if (tid < 672) {
            int og = tid / 96, px = tid % 96;
            int o0 = og * 3;
            float q0 = sCv[o0 + 0], q1 = sCv[o0 + 1], q2 = sCv[o0 + 2];
            #pragma unroll
            for (int c = 0; c < NC; c++) {
                float sp = sSp[c * 96 + px], bl = sBl[c * 96 + px];
                q0 += sW1[(o0 + 0) * NC + c] * sp + sW2[(o0 + 0) * NC + c] * bl;
                q1 += sW1[(o0 + 1) * NC + c] * sp + sW2[(o0 + 1) * NC + c] * bl;
                q2 += sW1[(o0 + 2) * NC + c] * sp + sW2[(o0 + 2) * NC + c] * bl;
            }
            sQ[(o0 + 0) * 96 + px] = expf(sU[(o0 + 0) * 96 + px] - q0);
            sQ[(o0 + 1) * 96 + px] = expf(sU[(o0 + 1) * 96 + px] - q1);
            sQ[(o0 + 2) * 96 + px] = expf(sU[(o0 + 2) * 96 + px] - q2);
        }
        __syncthreads();

        // ---- stage 4: normalize (+ final output) ---------------------------
        if (tid < HW) {
            int px = tid;
            float ss = 0.0f;
            #pragma unroll
            for (int o = 0; o < NC; o++) ss += sQ[o * 96 + px];
            float inv = 1.0f / ss;
            #pragma unroll
            for (int o = 0; o < NC; o++) {
                float sv = sQ[o * 96 + px] * inv;
                sS[o * 128 + 16 + px] = sv;
                if (it == 4) out[o * NPIX + y * HW + px] = sv;
            }
        }
        if (it == 4) break;                  // buf0 already zeroed (zrb=0)
        __syncthreads();

        // ---- stage 5: next moments partials | spX --------------------------
        if (tid < 392) {
            int quarter = tid / 98, r2 = tid % 98;
            int cg = r2 / 14, rg = r2 % 14;
            int r0 = rg * 4, c0 = cg * 3;
            ull acc[12];
            #pragma unroll
            for (int k = 0; k < 12; k++) acc[k] = 0ull;
            int p0 = quarter * 12;
            for (int p = p0; p < p0 + 12; p++) {
                ull ph0 = *(const ull*)(sPhi + (r0 + 0) * PHS + 2 * p);
                ull ph1 = *(const ull*)(sPhi + (r0 + 1) * PHS + 2 * p);
                ull ph2 = *(const ull*)(sPhi + (r0 + 2) * PHS + 2 * p);
                ull ph3 = *(const ull*)(sPhi + (r0 + 3) * PHS + 2 * p);
                #pragma unroll
                for (int j = 0; j < 3; j++) {
                    ull sv = *(const ull*)(sS + (c0 + j) * 128 + 16 + 2 * p);
                    fma2(acc[j * 4 + 0], ph0, sv);
                    fma2(acc[j * 4 + 1], ph1, sv);
                    fma2(acc[j * 4 + 2], ph2, sv);
                    fma2(acc[j * 4 + 3], ph3, sv);
                }
            }
            #pragma unroll
            for (int j = 0; j < 3; j++)
                #pragma unroll
                for (int i = 0; i < 4; i++)
                    sMomP[quarter * NMOM + (c0 + j) * RD + r0 + i] =
                        lo2(acc[j * 4 + i]) + hi2(acc[j * 4 + i]);
        } else {
            for (int t = tid - 392; t < NC * HW; t += TPB - 392) {
                int c = t / HW, x = t % HW;
                const float* sr = sS + c * 128 + x;
                float acc = 0.0f;
                #pragma unroll
                for (int d = 0; d < KW; d++) acc += sKer[d] * sr[d];
                g_tmpP[(c * TROWS + KR + y) * HW + x] = acc;
            }
        }
        __syncthreads();
        // stage 5b: reduce partials -> mom[wrb]
        for (int t = tid; t < NMOM; t += TPB) {
            float v = sMomP[t] + sMomP[NMOM + t] + sMomP[2 * NMOM + t] + sMomP[3 * NMOM + t];
            atomicAdd(&g_mom[wrb * NMOM + t], v);
        }
        gsync();                             // barriers #2..#5
    }
}

// ------------------------------ launch -------------------------------------
extern "C" void kernel_launch(void* const* d_in, const int* in_sizes, int n_in,
                              void* d_out, int out_size) {
    const float* image  = (const float*)d_in[0];
    const float* net_w  = (const float*)d_in[1];
    const float* net_b  = (const float*)d_in[2];
    const float* sp_w   = (const float*)d_in[3];
    const float* sp_b   = (const float*)d_in[4];
    const float* bl_w   = (const float*)d_in[5];
    const float* bl_b   = (const float*)d_in[6];
    const float* comp_w = (const float*)d_in[7];
    const float* comp_b = (const float*)d_in[8];
    float* out = (float*)d_out;

    static int smem_set = 0;
    if (!smem_set) {
        cudaFuncSetAttribute(crf_all, cudaFuncAttributeMaxDynamicSharedMemorySize,
                             SMEM_BYTES);
        smem_set = 1;
    }
    crf_all<<<GRID, TPB, SMEM_BYTES>>>(image, net_w, net_b, sp_w, sp_b,
                                       bl_w, bl_b, comp_w, comp_b, out);
}

// round 12
// speedup vs baseline: 3.8077x; 1.1918x over previous
#include <cuda_runtime.h>
#include <math.h>

// ---------------------------------------------------------------------------
// CRF-as-RNN forward — persistent kernel v7, owner-computes + mix-folding.
//  - 96 blocks x 1024 threads; block b owns image row y=b
//  - mixing matrices folded into filter inputs: t1=W1·s, t2=W2·s;
//    pairwise = F(t1)·gix + (phi^T · moments(t2))·nbI + cvec
//  - s never materialized: exp(q) + per-pixel inv carried instead
//  - deg-3 bilateral feature map (R=56), spatial Gaussian +-12 taps
//  - 5 grid barriers total; zero-invariants self-sustaining across replays
// ---------------------------------------------------------------------------

typedef unsigned long long ull;

static constexpr int HW   = 96;
static constexpr int NPIX = HW * HW;
static constexpr int NC   = 21;
static constexpr int RD   = 56;
static constexpr int GRID = 96;
static constexpr int TPB  = 1024;
static constexpr int NTHR = GRID * TPB;
static constexpr int KR   = 12;
static constexpr int KW   = 2 * KR + 1;     // 25
static constexpr int TROWS = HW + 2 * KR;   // 120
static constexpr int NMOM = NC * RD;        // 1176
static constexpr int PHS  = 104;

// smem float offsets (all multiples of 4)
static constexpr int O_MFD  = 0;                    // 1176 ull
static constexpr int O_MOMP = 2352;                 // 4*1176
static constexpr int O_PHI  = 7056;                 // 56*104
static constexpr int O_Q    = 12880;                // 21*96
static constexpr int O_U    = 14896;                // 21*96
static constexpr int O_T1   = 16912;                // 21*128 (x-padded, +16)
static constexpr int O_T2   = 19600;                // 21*96
static constexpr int O_SP   = 21616;                // 21*96
static constexpr int O_BLP  = 23632;                // 2*21*96
static constexpr int O_W1D  = 27664;                // 441 ull
static constexpr int O_W2D  = 28548;                // 441 ull
static constexpr int O_CV   = 29432;                // 24
static constexpr int O_KER  = 29456;                // 28
static constexpr int O_GSX  = 29484;                // 96
static constexpr int O_GIX  = 29580;                // 96
static constexpr int O_NBI  = 29676;                // 96
static constexpr int O_IV   = 29772;                // 96
static constexpr int O_IMG  = 29868;                // 864
static constexpr int O_NW   = 30732;                // 568
static constexpr int O_NB   = 31300;                // 28
static constexpr int SMEMF  = 31328;
static constexpr int SMEM_BYTES = SMEMF * 4;        // ~122.4 KB

// ------------------------- device scratch ----------------------------------
// g_tmpP border rows (0..11, 108..119) zero at module load, never written.
__device__ __align__(16) float g_tmpP[NC * TROWS * HW];
__device__ float g_mom[3 * NMOM];           // triple-buffered; zero-invariant
__device__ float g_M0[RD];                  // zero-invariant
__device__ unsigned g_barCount = 0, g_barGen = 0;

__device__ __forceinline__ void gsync() {
    __syncthreads();
    if (threadIdx.x == 0) {
        unsigned* cnt = &g_barCount;
        unsigned* gen = &g_barGen;
        unsigned my;
        asm volatile("ld.relaxed.gpu.u32 %0, [%1];" : "=r"(my) : "l"(gen));
        unsigned prev;
        asm volatile("atom.add.release.gpu.u32 %0, [%1], 1;"
                     : "=r"(prev) : "l"(cnt) : "memory");
        if (prev == GRID - 1u) {
            asm volatile("st.relaxed.gpu.u32 [%0], %1;" :: "l"(cnt), "r"(0u));
            asm volatile("st.release.gpu.u32 [%0], %1;"
                         :: "l"(gen), "r"(my + 1u) : "memory");
        } else {
            unsigned cur;
            do {
                __nanosleep(32);
                asm volatile("ld.acquire.gpu.u32 %0, [%1];"
                             : "=r"(cur) : "l"(gen) : "memory");
            } while (cur == my);
        }
    }
    __syncthreads();
}

__device__ __forceinline__ void fma2(ull& acc, ull a, ull b) {
    asm("fma.rn.f32x2 %0, %1, %2, %0;" : "+l"(acc) : "l"(a), "l"(b));
}
__device__ __forceinline__ ull dup2(float v) {
    unsigned u = __float_as_uint(v);
    return ((ull)u << 32) | (ull)u;
}
__device__ __forceinline__ float lo2(ull a) { return __uint_as_float((unsigned)a); }
__device__ __forceinline__ float hi2(ull a) { return __uint_as_float((unsigned)(a >> 32)); }

__global__ __launch_bounds__(TPB, 1) void crf_all(
    const float* __restrict__ img,
    const float* __restrict__ net_w, const float* __restrict__ net_b,
    const float* __restrict__ sp_w,  const float* __restrict__ sp_b,
    const float* __restrict__ bl_w,  const float* __restrict__ bl_b,
    const float* __restrict__ comp_w,const float* __restrict__ comp_b,
    float* __restrict__ out)
{
    extern __shared__ float sm[];
    ull*   sMfD = (ull*)(sm + O_MFD);
    float* sMomP= sm + O_MOMP;
    float* sPhi = sm + O_PHI;
    float* sQ   = sm + O_Q;
    float* sU   = sm + O_U;
    float* sT1  = sm + O_T1;      // stride 128, data at +16
    float* sT2  = sm + O_T2;
    float* sSp  = sm + O_SP;
    float* sBlP = sm + O_BLP;     // two halves of 2016
    ull*   sW1D = (ull*)(sm + O_W1D);
    ull*   sW2D = (ull*)(sm + O_W2D);
    float* sCv  = sm + O_CV;
    float* sKer = sm + O_KER;
    float* sGsx = sm + O_GSX;
    float* sGix = sm + O_GIX;
    float* sNbI = sm + O_NBI;
    float* sIv  = sm + O_IV;
    float* sImg = sm + O_IMG;
    float* sNw  = sm + O_NW;
    float* sNb  = sm + O_NB;

    const int tid  = threadIdx.x;
    const int y    = blockIdx.x;
    const int gtid = y * TPB + tid;

    // =================== setup (a): loads + global zeroing ==================
    for (int t = gtid; t < 2 * NMOM; t += NTHR) g_mom[NMOM + t] = 0.0f;
    for (int t = tid; t < KW; t += TPB) {
        float d = (float)(t - KR) * (1.0f / 3.0f);
        sKer[t] = expf(-0.5f * d * d);
    }
    for (int t = tid; t < 567; t += TPB) sNw[t] = net_w[t];
    for (int t = tid; t < NC; t += TPB) sNb[t] = net_b[t];
    for (int t = tid; t < 3 * 3 * HW; t += TPB) {
        int c = t / 288, rem = t % 288;
        int ry = rem / 96, x = rem % 96;
        int yy = y + ry - 1;
        sImg[t] = (yy >= 0 && yy < HW) ? img[c * NPIX + yy * HW + x] : 0.0f;
    }
    for (int t = tid; t < NC * NC; t += TPB) {
        int o = t / NC, k = t % NC;
        float a1 = 0.0f, a2 = 0.0f;
        for (int c = 0; c < NC; c++) {
            a1 += comp_w[o * NC + c] * sp_w[c * NC + k];
            a2 += comp_w[o * NC + c] * bl_w[c * NC + k];
        }
        sW1D[t] = dup2(a1);
        sW2D[t] = dup2(a2);
    }
    for (int t = tid; t < NC; t += TPB) {
        float cv = comp_b[t];
        for (int c = 0; c < NC; c++) cv += comp_w[t * NC + c] * (sp_b[c] + bl_b[c]);
        sCv[t] = cv;
    }
    __syncthreads();

    // =================== setup (b): gsx + phi | unary =======================
    if (tid < HW) {
        int px = tid;
        float acc = 0.0f;
        #pragma unroll
        for (int d = 0; d < KW; d++) {
            int xx = px + d - KR;
            if (xx >= 0 && xx < HW) acc += sKer[d];
        }
        sGsx[px] = acc;
        float f0 = ((float)px - 47.5f) * (1.0f / 160.0f);
        float f1 = ((float)y  - 47.5f) * (1.0f / 160.0f);
        float f2 = (sImg[0 * 288 + 96 + px] - 0.5f) * (1.0f / 3.0f);
        float f3 = (sImg[1 * 288 + 96 + px] - 0.5f) * (1.0f / 3.0f);
        float f4 = (sImg[2 * 288 + 96 + px] - 0.5f) * (1.0f / 3.0f);
        float a = expf(-0.5f * (f0*f0 + f1*f1 + f2*f2 + f3*f3 + f4*f4));
        const float I2 = 0.70710678f, I3 = 0.57735027f;
        int r = 0;
        float v0 = a;
        for (int m0 = 0; m0 <= 3; m0++) {
            float v1 = v0;
            for (int m1 = 0; m1 <= 3 - m0; m1++) {
                float v2 = v1;
                for (int m2 = 0; m2 <= 3 - m0 - m1; m2++) {
                    float v3 = v2;
                    for (int m3 = 0; m3 <= 3 - m0 - m1 - m2; m3++) {
                        float v4 = v3;
                        for (int m4 = 0; m4 <= 3 - m0 - m1 - m2 - m3; m4++) {
                            sPhi[r * PHS + px] = v4;
                            r++;
                            v4 *= f4 * (m4 == 0 ? 1.0f : m4 == 1 ? I2 : I3);
                        }
                        v3 *= f3 * (m3 == 0 ? 1.0f : m3 == 1 ? I2 : I3);
                    }
                    v2 *= f2 * (m2 == 0 ? 1.0f : m2 == 1 ? I2 : I3);
                }
                v1 *= f1 * (m1 == 0 ? 1.0f : m1 == 1 ? I2 : I3);
            }
            v0 *= f0 * (m0 == 0 ? 1.0f : m0 == 1 ? I2 : I3);
        }
    } else {
        for (int t = tid - 96; t < NC * HW; t += TPB - 96) {
            int o = t / HW, x = t % HW;
            float acc = sNb[o];
            #pragma unroll
            for (int c = 0; c < 3; c++)
                #pragma unroll
                for (int ky = 0; ky < 3; ky++)
                    #pragma unroll
                    for (int kx = 0; kx < 3; kx++) {
                        int xx = x + kx - 1;
                        if (xx < 0 || xx >= HW) continue;
                        acc += sImg[c * 288 + ky * 96 + xx]
                             * sNw[((o * 3 + c) * 3 + ky) * 3 + kx];
                    }
            sU[t] = acc;
        }
    }
    __syncthreads();

    // ====== setup (c): gix | exp(u) | M0 atomics | zero sT1 pads ============
    if (tid < HW) {
        sGix[tid] = 1.0f / (sGsx[y] * sGsx[tid]);
    } else if (tid < 768) {
        for (int u2 = tid - 96; u2 < NC * HW; u2 += 672) sQ[u2] = expf(sU[u2]);
    } else if (tid < 768 + RD) {
        int r = tid - 768;
        float acc = 0.0f;
        for (int px = 0; px < HW; px++) acc += sPhi[r * PHS + px];
        atomicAdd(&g_M0[r], acc);            // zeroed by prev launch (it==2)
    } else {
        for (int i = tid - 824; i < NC * 32; i += 200) {
            int c = i / 32, j = i % 32;
            sT1[c * 128 + (j < 16 ? j : 96 + j)] = 0.0f;
        }
    }
    __syncthreads();

    // ====== setup (d): inv-sum =============================================
    if (tid < HW) {
        int px = tid;
        float ss = 0.0f;
        #pragma unroll
        for (int o = 0; o < NC; o++) ss += sQ[o * 96 + px];
        sIv[px] = 1.0f / ss;
    }
    __syncthreads();

    // ====== setup (e): mix t1=W1·s, t2=W2·s ================================
    if (tid < 336) {
        int og = tid / 48, pp = tid % 48;
        int o0 = og * 3;
        ull t1a[3] = {0, 0, 0}, t2a[3] = {0, 0, 0};
        for (int c = 0; c < NC; c++) {
            ull sv = *(const ull*)(sQ + c * 96 + 2 * pp);
            #pragma unroll
            for (int k = 0; k < 3; k++) {
                fma2(t1a[k], sv, sW1D[(o0 + k) * NC + c]);
                fma2(t2a[k], sv, sW2D[(o0 + k) * NC + c]);
            }
        }
        float i0 = sIv[2 * pp], i1 = sIv[2 * pp + 1];
        #pragma unroll
        for (int k = 0; k < 3; k++) {
            sT1[(o0 + k) * 128 + 16 + 2 * pp]     = lo2(t1a[k]) * i0;
            sT1[(o0 + k) * 128 + 16 + 2 * pp + 1] = hi2(t1a[k]) * i1;
            sT2[(o0 + k) * 96 + 2 * pp]           = lo2(t2a[k]) * i0;
            sT2[(o0 + k) * 96 + 2 * pp + 1]       = hi2(t2a[k]) * i1;
        }
    }
    __syncthreads();

    // ====== setup (f): spX(t1) | moments(t2) ===============================
    if (tid < 504) {
        int c = tid / 24, q4 = tid % 24;
        float w[28];
        const float* base = sT1 + c * 128 + 4 + 4 * q4;
        #pragma unroll
        for (int i = 0; i < 7; i++) *(float4*)(w + 4 * i) = *(const float4*)(base + 4 * i);
        float a0 = 0.f, a1 = 0.f, a2 = 0.f, a3 = 0.f;
        #pragma unroll
        for (int d = 0; d < KW; d++) {
            float k = sKer[d];
            a0 += k * w[d]; a1 += k * w[d + 1]; a2 += k * w[d + 2]; a3 += k * w[d + 3];
        }
        *(float4*)(g_tmpP + (c * TROWS + KR + y) * HW + 4 * q4) = make_float4(a0, a1, a2, a3);
    } else if (tid >= 512 && tid < 904) {
        int u2 = tid - 512;
        int quarter = u2 / 98, r2 = u2 % 98;
        int cg = r2 / 14, rg = r2 % 14;
        int r0 = rg * 4, c0 = cg * 3;
        ull acc[12];
        #pragma unroll
        for (int k = 0; k < 12; k++) acc[k] = 0ull;
        int p0 = quarter * 12;
        for (int p = p0; p < p0 + 12; p++) {
            ull ph0 = *(const ull*)(sPhi + (r0 + 0) * PHS + 2 * p);
            ull ph1 = *(const ull*)(sPhi + (r0 + 1) * PHS + 2 * p);
            ull ph2 = *(const ull*)(sPhi + (r0 + 2) * PHS + 2 * p);
            ull ph3 = *(const ull*)(sPhi + (r0 + 3) * PHS + 2 * p);
            #pragma unroll
            for (int j = 0; j < 3; j++) {
                ull sv = *(const ull*)(sT2 + (c0 + j) * 96 + 2 * p);
                fma2(acc[j * 4 + 0], ph0, sv);
                fma2(acc[j * 4 + 1], ph1, sv);
                fma2(acc[j * 4 + 2], ph2, sv);
                fma2(acc[j * 4 + 3], ph3, sv);
            }
        }
        #pragma unroll
        for (int j = 0; j < 3; j++)
            #pragma unroll
            for (int i = 0; i < 4; i++)
                sMomP[quarter * NMOM + (c0 + j) * RD + r0 + i] =
                    lo2(acc[j * 4 + i]) + hi2(acc[j * 4 + i]);
    }
    __syncthreads();
    // setup (g): reduce -> mom buffer 0 (zeroed by prev launch at it1/it4)
    for (int t = tid; t < NMOM; t += TPB) {
        float v = sMomP[t] + sMomP[NMOM + t] + sMomP[2 * NMOM + t] + sMomP[3 * NMOM + t];
        atomicAdd(&g_mom[t], v);
    }
    gsync();                                 // barrier #1

    // ======================= mean-field iterations ==========================
    for (int it = 0; it < 5; it++) {
        const int rdb = it % 3, wrb = (it + 1) % 3, zrb = (it + 2) % 3;

        // ---- S1: dup-load moments, zero future buffer, [it0: nbI] ----------
        for (int t = tid; t < NMOM; t += TPB) sMfD[t] = dup2(g_mom[rdb * NMOM + t]);
        for (int t = tid; t < NMOM; t += TPB) g_mom[zrb * NMOM + t] = 0.0f;
        if (it == 0 && tid < HW) {
            int px = tid;
            float acc = 0.0f;
            for (int r = 0; r < RD; r++) acc += sPhi[r * PHS + px] * g_M0[r];
            sNbI[px] = 1.0f / acc;
        }
        if (it == 2 && tid >= 128 && tid < 128 + RD) g_M0[tid - 128] = 0.0f;
        __syncthreads();

        // ---- S2: bl partials (0..335) | spY (512..1015) --------------------
        if (tid < 336) {
            int rh = tid / 168, u2 = tid % 168;
            int cg = u2 / 24, q4 = u2 % 24;
            int c0 = cg * 3;
            ull a[6];
            #pragma unroll
            for (int k = 0; k < 6; k++) a[k] = 0ull;
            int rbase = rh * 28;
            for (int rr = 0; rr < 28; rr++) {
                int r = rbase + rr;
                ulonglong2 ph = *(const ulonglong2*)(sPhi + r * PHS + 4 * q4);
                #pragma unroll
                for (int k = 0; k < 3; k++) {
                    ull m = sMfD[(c0 + k) * RD + r];
                    fma2(a[2 * k], ph.x, m);
                    fma2(a[2 * k + 1], ph.y, m);
                }
            }
            float* dst = sBlP + rh * 2016;
            #pragma unroll
            for (int k = 0; k < 3; k++) {
                dst[(c0 + k) * 96 + 4 * q4 + 0] = lo2(a[2 * k]);
                dst[(c0 + k) * 96 + 4 * q4 + 1] = hi2(a[2 * k]);
                dst[(c0 + k) * 96 + 4 * q4 + 2] = lo2(a[2 * k + 1]);
                dst[(c0 + k) * 96 + 4 * q4 + 3] = hi2(a[2 * k + 1]);
            }
        } else if (tid >= 512 && tid < 1016) {
            int u2 = tid - 512;
            int c = u2 / 24, q4 = u2 % 24;
            float4 a = make_float4(0.f, 0.f, 0.f, 0.f);
            const float* base = g_tmpP + (c * TROWS + y) * HW + 4 * q4;
            #pragma unroll
            for (int d = 0; d < KW; d++) {
                float4 tv = *(const float4*)(base + d * HW);
                float k = sKer[d];
                a.x += tv.x * k; a.y += tv.y * k;
                a.z += tv.z * k; a.w += tv.w * k;
            }
            int px = 4 * q4;
            sSp[c * 96 + px + 0] = a.x * sGix[px + 0];
            sSp[c * 96 + px + 1] = a.y * sGix[px + 1];
            sSp[c * 96 + px + 2] = a.z * sGix[px + 2];
            sSp[c * 96 + px + 3] = a.w * sGix[px + 3];
        }
        __syncthreads();

        // ---- S3: q = u - cvec - sp - bl; exp -------------------------------
        if (tid < 672) {
            #pragma unroll
            for (int j = 0; j < 3; j++) {
                int idx = tid + j * 672;
                int o = idx / 96, px = idx % 96;
                float bl = (sBlP[idx] + sBlP[2016 + idx]) * sNbI[px];
                float q = sU[idx] - sCv[o] - sSp[idx] - bl;
                sQ[idx] = expf(q);
            }
        }
        __syncthreads();

        // ---- S4: inv-sum (+ final output) ----------------------------------
        if (tid < HW) {
            int px = tid;
            float ss = 0.0f;
            #pragma unroll
            for (int o = 0; o < NC; o++) ss += sQ[o * 96 + px];
            float inv = 1.0f / ss;
            sIv[px] = inv;
            if (it == 4) {
                #pragma unroll
                for (int o = 0; o < NC; o++)
                    out[o * NPIX + y * HW + px] = sQ[o * 96 + px] * inv;
            }
        }
        if (it == 4) break;
        __syncthreads();

        // ---- S5: mix t1, t2 ------------------------------------------------
        if (tid < 336) {
            int og = tid / 48, pp = tid % 48;
            int o0 = og * 3;
            ull t1a[3] = {0, 0, 0}, t2a[3] = {0, 0, 0};
            for (int c = 0; c < NC; c++) {
                ull sv = *(const ull*)(sQ + c * 96 + 2 * pp);
                #pragma unroll
                for (int k = 0; k < 3; k++) {
                    fma2(t1a[k], sv, sW1D[(o0 + k) * NC + c]);
                    fma2(t2a[k], sv, sW2D[(o0 + k) * NC + c]);
                }
            }
            float i0 = sIv[2 * pp], i1 = sIv[2 * pp + 1];
            #pragma unroll
            for (int k = 0; k < 3; k++) {
                sT1[(o0 + k) * 128 + 16 + 2 * pp]     = lo2(t1a[k]) * i0;
                sT1[(o0 + k) * 128 + 16 + 2 * pp + 1] = hi2(t1a[k]) * i1;
                sT2[(o0 + k) * 96 + 2 * pp]           = lo2(t2a[k]) * i0;
                sT2[(o0 + k) * 96 + 2 * pp + 1]       = hi2(t2a[k]) * i1;
            }
        }
        __syncthreads();

        // ---- S6: spX(t1) | moments(t2) -------------------------------------
        if (tid < 504) {
            int c = tid / 24, q4 = tid % 24;
            float w[28];
            const float* base = sT1 + c * 128 + 4 + 4 * q4;
            #pragma unroll
            for (int i = 0; i < 7; i++) *(float4*)(w + 4 * i) = *(const float4*)(base + 4 * i);
            float a0 = 0.f, a1 = 0.f, a2 = 0.f, a3 = 0.f;
            #pragma unroll
            for (int d = 0; d < KW; d++) {
                float k = sKer[d];
                a0 += k * w[d]; a1 += k * w[d + 1]; a2 += k * w[d + 2]; a3 += k * w[d + 3];
            }
            *(float4*)(g_tmpP + (c * TROWS + KR + y) * HW + 4 * q4) = make_float4(a0, a1, a2, a3);
        } else if (tid >= 512 && tid < 904) {
            int u2 = tid - 512;
            int quarter = u2 / 98, r2 = u2 % 98;
            int cg = r2 / 14, rg = r2 % 14;
            int r0 = rg * 4, c0 = cg * 3;
            ull acc[12];
            #pragma unroll
            for (int k = 0; k < 12; k++) acc[k] = 0ull;
            int p0 = quarter * 12;
            for (int p = p0; p < p0 + 12; p++) {
                ull ph0 = *(const ull*)(sPhi + (r0 + 0) * PHS + 2 * p);
                ull ph1 = *(const ull*)(sPhi + (r0 + 1) * PHS + 2 * p);
                ull ph2 = *(const ull*)(sPhi + (r0 + 2) * PHS + 2 * p);
                ull ph3 = *(const ull*)(sPhi + (r0 + 3) * PHS + 2 * p);
                #pragma unroll
                for (int j = 0; j < 3; j++) {
                    ull sv = *(const ull*)(sT2 + (c0 + j) * 96 + 2 * p);
                    fma2(acc[j * 4 + 0], ph0, sv);
                    fma2(acc[j * 4 + 1], ph1, sv);
                    fma2(acc[j * 4 + 2], ph2, sv);
                    fma2(acc[j * 4 + 3], ph3, sv);
                }
            }
            #pragma unroll
            for (int j = 0; j < 3; j++)
                #pragma unroll
                for (int i = 0; i < 4; i++)
                    sMomP[quarter * NMOM + (c0 + j) * RD + r0 + i] =
                        lo2(acc[j * 4 + i]) + hi2(acc[j * 4 + i]);
        }
        __syncthreads();
        // ---- S6b: reduce -> mom[wrb] ---------------------------------------
        for (int t = tid; t < NMOM; t += TPB) {
            float v = sMomP[t] + sMomP[NMOM + t] + sMomP[2 * NMOM + t] + sMomP[3 * NMOM + t];
            atomicAdd(&g_mom[wrb * NMOM + t], v);
        }
        gsync();                             // barriers #2..#5
    }
}

// ------------------------------ launch -------------------------------------
extern "C" void kernel_launch(void* const* d_in, const int* in_sizes, int n_in,
                              void* d_out, int out_size) {
    const float* image  = (const float*)d_in[0];
    const float* net_w  = (const float*)d_in[1];
    const float* net_b  = (const float*)d_in[2];
    const float* sp_w   = (const float*)d_in[3];
    const float* sp_b   = (const float*)d_in[4];
    const float* bl_w   = (const float*)d_in[5];
    const float* bl_b   = (const float*)d_in[6];
    const float* comp_w = (const float*)d_in[7];
    const float* comp_b = (const float*)d_in[8];
    float* out = (float*)d_out;

    static int smem_set = 0;
    if (!smem_set) {
        cudaFuncSetAttribute(crf_all, cudaFuncAttributeMaxDynamicSharedMemorySize,
                             SMEM_BYTES);
        smem_set = 1;
    }
    crf_all<<<GRID, TPB, SMEM_BYTES>>>(image, net_w, net_b, sp_w, sp_b,
                                       bl_w, bl_b, comp_w, comp_b, out);
}

// round 13
// speedup vs baseline: 5.1383x; 1.3494x over previous
#include <cuda_runtime.h>
#include <math.h>

// ---------------------------------------------------------------------------
// CRF-as-RNN forward — persistent kernel v8, owner-computes + mix-folding.
//  - 96 blocks x 1024 threads; block b owns image row y=b
//  - mixing matrices folded into filter inputs: t1=W1·s, t2=W2·s
//  - bilateral: deg-2 Taylor feature map, R=21 monomials
//    (truncation cancels in normalized ratio; empirically ~1e-6 rel err)
//  - spatial Gaussian +-12 taps; 5 grid barriers total
//  - zero-invariants self-sustaining across graph replays
// ---------------------------------------------------------------------------

typedef unsigned long long ull;

static constexpr int HW   = 96;
static constexpr int NPIX = HW * HW;
static constexpr int NC   = 21;
static constexpr int RD   = 21;             // monomials deg<=2 in 5 vars
static constexpr int GRID = 96;
static constexpr int TPB  = 1024;
static constexpr int NTHR = GRID * TPB;
static constexpr int KR   = 12;
static constexpr int KW   = 2 * KR + 1;     // 25
static constexpr int TROWS = HW + 2 * KR;   // 120
static constexpr int NMOM = NC * RD;        // 441
static constexpr int PHS  = 104;

// smem float offsets (all multiples of 4)
static constexpr int O_MFD  = 0;                    // 441 ull = 882 f
static constexpr int O_MOMP = 884;                  // 4*441 = 1764
static constexpr int O_PHI  = 2648;                 // 21*104 = 2184
static constexpr int O_Q    = 4832;                 // 2016
static constexpr int O_U    = 6848;                 // 2016
static constexpr int O_T1   = 8864;                 // 21*128 (x-padded, +16)
static constexpr int O_T2   = 11552;                // 2016
static constexpr int O_SP   = 13568;                // 2016
static constexpr int O_BLP  = 15584;                // 3*2016 = 6048
static constexpr int O_W1D  = 21632;                // 441 ull = 882
static constexpr int O_W2D  = 22516;                // 882
static constexpr int O_CV   = 23400;                // 24
static constexpr int O_KER  = 23424;                // 28
static constexpr int O_GSX  = 23452;                // 96
static constexpr int O_GIX  = 23548;                // 96
static constexpr int O_NBI  = 23644;                // 96
static constexpr int O_IV   = 23740;                // 96
static constexpr int O_IMG  = 23836;                // 864
static constexpr int O_NW   = 24700;                // 568
static constexpr int O_NB   = 25268;                // 28
static constexpr int SMEMF  = 25296;
static constexpr int SMEM_BYTES = SMEMF * 4;        // ~98.8 KB

// ------------------------- device scratch ----------------------------------
// g_tmpP border rows (0..11, 108..119) zero at module load, never written.
__device__ __align__(16) float g_tmpP[NC * TROWS * HW];
__device__ float g_mom[3 * NMOM];           // triple-buffered; zero-invariant
__device__ float g_M0[RD];                  // zero-invariant
__device__ unsigned g_barCount = 0, g_barGen = 0;

__device__ __forceinline__ void gsync() {
    __syncthreads();
    if (threadIdx.x == 0) {
        unsigned* cnt = &g_barCount;
        unsigned* gen = &g_barGen;
        unsigned my;
        asm volatile("ld.relaxed.gpu.u32 %0, [%1];" : "=r"(my) : "l"(gen));
        unsigned prev;
        asm volatile("atom.add.release.gpu.u32 %0, [%1], 1;"
                     : "=r"(prev) : "l"(cnt) : "memory");
        if (prev == GRID - 1u) {
            asm volatile("st.relaxed.gpu.u32 [%0], %1;" :: "l"(cnt), "r"(0u));
            asm volatile("st.release.gpu.u32 [%0], %1;"
                         :: "l"(gen), "r"(my + 1u) : "memory");
        } else {
            unsigned cur;
            do {
                __nanosleep(32);
                asm volatile("ld.acquire.gpu.u32 %0, [%1];"
                             : "=r"(cur) : "l"(gen) : "memory");
            } while (cur == my);
        }
    }
    __syncthreads();
}

__device__ __forceinline__ void fma2(ull& acc, ull a, ull b) {
    asm("fma.rn.f32x2 %0, %1, %2, %0;" : "+l"(acc) : "l"(a), "l"(b));
}
__device__ __forceinline__ ull dup2(float v) {
    unsigned u = __float_as_uint(v);
    return ((ull)u << 32) | (ull)u;
}
__device__ __forceinline__ float lo2(ull a) { return __uint_as_float((unsigned)a); }
__device__ __forceinline__ float hi2(ull a) { return __uint_as_float((unsigned)(a >> 32)); }

__global__ __launch_bounds__(TPB, 1) void crf_all(
    const float* __restrict__ img,
    const float* __restrict__ net_w, const float* __restrict__ net_b,
    const float* __restrict__ sp_w,  const float* __restrict__ sp_b,
    const float* __restrict__ bl_w,  const float* __restrict__ bl_b,
    const float* __restrict__ comp_w,const float* __restrict__ comp_b,
    float* __restrict__ out)
{
    extern __shared__ float sm[];
    ull*   sMfD = (ull*)(sm + O_MFD);
    float* sMomP= sm + O_MOMP;
    float* sPhi = sm + O_PHI;
    float* sQ   = sm + O_Q;
    float* sU   = sm + O_U;
    float* sT1  = sm + O_T1;      // stride 128, data at +16
    float* sT2  = sm + O_T2;
    float* sSp  = sm + O_SP;
    float* sBlP = sm + O_BLP;     // three 2016-float partial planes
    ull*   sW1D = (ull*)(sm + O_W1D);
    ull*   sW2D = (ull*)(sm + O_W2D);
    float* sCv  = sm + O_CV;
    float* sKer = sm + O_KER;
    float* sGsx = sm + O_GSX;
    float* sGix = sm + O_GIX;
    float* sNbI = sm + O_NBI;
    float* sIv  = sm + O_IV;
    float* sImg = sm + O_IMG;
    float* sNw  = sm + O_NW;
    float* sNb  = sm + O_NB;

    const int tid  = threadIdx.x;
    const int y    = blockIdx.x;
    const int gtid = y * TPB + tid;

    // =================== setup (a): loads + global zeroing ==================
    for (int t = gtid; t < 2 * NMOM; t += NTHR) g_mom[NMOM + t] = 0.0f;
    for (int t = tid; t < KW; t += TPB) {
        float d = (float)(t - KR) * (1.0f / 3.0f);
        sKer[t] = expf(-0.5f * d * d);
    }
    for (int t = tid; t < 567; t += TPB) sNw[t] = net_w[t];
    for (int t = tid; t < NC; t += TPB) sNb[t] = net_b[t];
    for (int t = tid; t < 3 * 3 * HW; t += TPB) {
        int c = t / 288, rem = t % 288;
        int ry = rem / 96, x = rem % 96;
        int yy = y + ry - 1;
        sImg[t] = (yy >= 0 && yy < HW) ? img[c * NPIX + yy * HW + x] : 0.0f;
    }
    for (int t = tid; t < NC * NC; t += TPB) {
        int o = t / NC, k = t % NC;
        float a1 = 0.0f, a2 = 0.0f;
        for (int c = 0; c < NC; c++) {
            a1 += comp_w[o * NC + c] * sp_w[c * NC + k];
            a2 += comp_w[o * NC + c] * bl_w[c * NC + k];
        }
        sW1D[t] = dup2(a1);
        sW2D[t] = dup2(a2);
    }
    for (int t = tid; t < NC; t += TPB) {
        float cv = comp_b[t];
        for (int c = 0; c < NC; c++) cv += comp_w[t * NC + c] * (sp_b[c] + bl_b[c]);
        sCv[t] = cv;
    }
    __syncthreads();

    // =================== setup (b): gsx + phi (deg-2) | unary ===============
    if (tid < HW) {
        int px = tid;
        float acc = 0.0f;
        #pragma unroll
        for (int d = 0; d < KW; d++) {
            int xx = px + d - KR;
            if (xx >= 0 && xx < HW) acc += sKer[d];
        }
        sGsx[px] = acc;
        float f0 = ((float)px - 47.5f) * (1.0f / 160.0f);
        float f1 = ((float)y  - 47.5f) * (1.0f / 160.0f);
        float f2 = (sImg[0 * 288 + 96 + px] - 0.5f) * (1.0f / 3.0f);
        float f3 = (sImg[1 * 288 + 96 + px] - 0.5f) * (1.0f / 3.0f);
        float f4 = (sImg[2 * 288 + 96 + px] - 0.5f) * (1.0f / 3.0f);
        float a = expf(-0.5f * (f0*f0 + f1*f1 + f2*f2 + f3*f3 + f4*f4));
        const float I2 = 0.70710678f;
        int r = 0;
        float v0 = a;
        for (int m0 = 0; m0 <= 2; m0++) {
            float v1 = v0;
            for (int m1 = 0; m1 <= 2 - m0; m1++) {
                float v2 = v1;
                for (int m2 = 0; m2 <= 2 - m0 - m1; m2++) {
                    float v3 = v2;
                    for (int m3 = 0; m3 <= 2 - m0 - m1 - m2; m3++) {
                        float v4 = v3;
                        for (int m4 = 0; m4 <= 2 - m0 - m1 - m2 - m3; m4++) {
                            sPhi[r * PHS + px] = v4;
                            r++;
                            v4 *= f4 * (m4 == 0 ? 1.0f : I2);
                        }
                        v3 *= f3 * (m3 == 0 ? 1.0f : I2);
                    }
                    v2 *= f2 * (m2 == 0 ? 1.0f : I2);
                }
                v1 *= f1 * (m1 == 0 ? 1.0f : I2);
            }
            v0 *= f0 * (m0 == 0 ? 1.0f : I2);
        }
    } else {
        for (int t = tid - 96; t < NC * HW; t += TPB - 96) {
            int o = t / HW, x = t % HW;
            float acc = sNb[o];
            #pragma unroll
            for (int c = 0; c < 3; c++)
                #pragma unroll
                for (int ky = 0; ky < 3; ky++)
                    #pragma unroll
                    for (int kx = 0; kx < 3; kx++) {
                        int xx = x + kx - 1;
                        if (xx < 0 || xx >= HW) continue;
                        acc += sImg[c * 288 + ky * 96 + xx]
                             * sNw[((o * 3 + c) * 3 + ky) * 3 + kx];
                    }
            sU[t] = acc;
        }
    }
    __syncthreads();

    // ====== setup (c): gix | exp(u) | M0 atomics | zero sT1 pads ============
    if (tid < HW) {
        sGix[tid] = 1.0f / (sGsx[y] * sGsx[tid]);
    } else if (tid < 768) {
        for (int u2 = tid - 96; u2 < NC * HW; u2 += 672) sQ[u2] = expf(sU[u2]);
    } else if (tid < 768 + RD) {
        int r = tid - 768;
        float acc = 0.0f;
        for (int px = 0; px < HW; px++) acc += sPhi[r * PHS + px];
        atomicAdd(&g_M0[r], acc);            // zeroed by prev launch (it==2)
    } else if (tid >= 824) {
        for (int i = tid - 824; i < NC * 32; i += 200) {
            int c = i / 32, j = i % 32;
            sT1[c * 128 + (j < 16 ? j : 96 + j)] = 0.0f;
        }
    }
    __syncthreads();

    // ====== setup (d): inv-sum =============================================
    if (tid < HW) {
        int px = tid;
        float ss = 0.0f;
        #pragma unroll
        for (int o = 0; o < NC; o++) ss += sQ[o * 96 + px];
        sIv[px] = 1.0f / ss;
    }
    __syncthreads();

    // ====== setup (e): mix t1=W1·s, t2=W2·s ================================
    if (tid < 336) {
        int og = tid / 48, pp = tid % 48;
        int o0 = og * 3;
        ull t1a[3] = {0, 0, 0}, t2a[3] = {0, 0, 0};
        for (int c = 0; c < NC; c++) {
            ull sv = *(const ull*)(sQ + c * 96 + 2 * pp);
            #pragma unroll
            for (int k = 0; k < 3; k++) {
                fma2(t1a[k], sv, sW1D[(o0 + k) * NC + c]);
                fma2(t2a[k], sv, sW2D[(o0 + k) * NC + c]);
            }
        }
        float i0 = sIv[2 * pp], i1 = sIv[2 * pp + 1];
        #pragma unroll
        for (int k = 0; k < 3; k++) {
            sT1[(o0 + k) * 128 + 16 + 2 * pp]     = lo2(t1a[k]) * i0;
            sT1[(o0 + k) * 128 + 16 + 2 * pp + 1] = hi2(t1a[k]) * i1;
            sT2[(o0 + k) * 96 + 2 * pp]           = lo2(t2a[k]) * i0;
            sT2[(o0 + k) * 96 + 2 * pp + 1]       = hi2(t2a[k]) * i1;
        }
    }
    __syncthreads();

    // ====== setup (f): spX(t1) | moments(t2) ===============================
    if (tid < 504) {
        int c = tid / 24, q4 = tid % 24;
        float w[28];
        const float* base = sT1 + c * 128 + 4 + 4 * q4;
        #pragma unroll
        for (int i = 0; i < 7; i++) *(float4*)(w + 4 * i) = *(const float4*)(base + 4 * i);
        float a0 = 0.f, a1 = 0.f, a2 = 0.f, a3 = 0.f;
        #pragma unroll
        for (int d = 0; d < KW; d++) {
            float k = sKer[d];
            a0 += k * w[d]; a1 += k * w[d + 1]; a2 += k * w[d + 2]; a3 += k * w[d + 3];
        }
        *(float4*)(g_tmpP + (c * TROWS + KR + y) * HW + 4 * q4) = make_float4(a0, a1, a2, a3);
    } else if (tid >= 512 && tid < 708) {
        int u2 = tid - 512;
        int quarter = u2 / 49, r2 = u2 % 49;
        int cg = r2 / 7, rg = r2 % 7;
        int r0 = rg * 3, c0 = cg * 3;
        ull acc[9];
        #pragma unroll
        for (int k = 0; k < 9; k++) acc[k] = 0ull;
        int p0 = quarter * 12;
        for (int p = p0; p < p0 + 12; p++) {
            ull ph0 = *(const ull*)(sPhi + (r0 + 0) * PHS + 2 * p);
            ull ph1 = *(const ull*)(sPhi + (r0 + 1) * PHS + 2 * p);
            ull ph2 = *(const ull*)(sPhi + (r0 + 2) * PHS + 2 * p);
            #pragma unroll
            for (int j = 0; j < 3; j++) {
                ull sv = *(const ull*)(sT2 + (c0 + j) * 96 + 2 * p);
                fma2(acc[j * 3 + 0], ph0, sv);
                fma2(acc[j * 3 + 1], ph1, sv);
                fma2(acc[j * 3 + 2], ph2, sv);
            }
        }
        #pragma unroll
        for (int j = 0; j < 3; j++)
            #pragma unroll
            for (int i = 0; i < 3; i++)
                sMomP[quarter * NMOM + (c0 + j) * RD + r0 + i] =
                    lo2(acc[j * 3 + i]) + hi2(acc[j * 3 + i]);
    }
    __syncthreads();
    // setup (g): reduce -> mom buffer 0 (zeroed by prev launch at it4)
    if (tid < NMOM) {
        float v = sMomP[tid] + sMomP[NMOM + tid]
                + sMomP[2 * NMOM + tid] + sMomP[3 * NMOM + tid];
        atomicAdd(&g_mom[tid], v);
    }
    gsync();                                 // barrier #1

    // ======================= mean-field iterations ==========================
    for (int it = 0; it < 5; it++) {
        const int rdb = it % 3, wrb = (it + 1) % 3, zrb = (it + 2) % 3;

        // ---- S1: dup-load moments | zero future buffer | [it0: nbI] --------
        if (tid < NMOM) {
            sMfD[tid] = dup2(g_mom[rdb * NMOM + tid]);
        } else if (tid < 2 * NMOM) {
            g_mom[zrb * NMOM + (tid - NMOM)] = 0.0f;
        } else if (it == 2 && tid >= 882 && tid < 882 + RD) {
            g_M0[tid - 882] = 0.0f;
        }
        if (it == 0 && tid >= 896 && tid < 896 + HW) {
            int px = tid - 896;
            float acc = 0.0f;
            for (int r = 0; r < RD; r++) acc += sPhi[r * PHS + px] * g_M0[r];
            sNbI[px] = 1.0f / acc;
        }
        __syncthreads();

        // ---- S2: bl partials (0..503) | spY (512..1015) --------------------
        if (tid < 504) {
            int rh = tid / 168, u2 = tid % 168;
            int cg = u2 / 24, q4 = u2 % 24;
            int c0 = cg * 3;
            ull a[6];
            #pragma unroll
            for (int k = 0; k < 6; k++) a[k] = 0ull;
            int rbase = rh * 7;
            #pragma unroll
            for (int rr = 0; rr < 7; rr++) {
                int r = rbase + rr;
                ulonglong2 ph = *(const ulonglong2*)(sPhi + r * PHS + 4 * q4);
                #pragma unroll
                for (int k = 0; k < 3; k++) {
                    ull m = sMfD[(c0 + k) * RD + r];
                    fma2(a[2 * k], ph.x, m);
                    fma2(a[2 * k + 1], ph.y, m);
                }
            }
            float* dst = sBlP + rh * 2016;
            #pragma unroll
            for (int k = 0; k < 3; k++) {
                dst[(c0 + k) * 96 + 4 * q4 + 0] = lo2(a[2 * k]);
                dst[(c0 + k) * 96 + 4 * q4 + 1] = hi2(a[2 * k]);
                dst[(c0 + k) * 96 + 4 * q4 + 2] = lo2(a[2 * k + 1]);
                dst[(c0 + k) * 96 + 4 * q4 + 3] = hi2(a[2 * k + 1]);
            }
        } else if (tid >= 512 && tid < 1016) {
            int u2 = tid - 512;
            int c = u2 / 24, q4 = u2 % 24;
            float4 a = make_float4(0.f, 0.f, 0.f, 0.f);
            const float* base = g_tmpP + (c * TROWS + y) * HW + 4 * q4;
            #pragma unroll
            for (int d = 0; d < KW; d++) {
                float4 tv = *(const float4*)(base + d * HW);
                float k = sKer[d];
                a.x += tv.x * k; a.y += tv.y * k;
                a.z += tv.z * k; a.w += tv.w * k;
            }
            int px = 4 * q4;
            sSp[c * 96 + px + 0] = a.x * sGix[px + 0];
            sSp[c * 96 + px + 1] = a.y * sGix[px + 1];
            sSp[c * 96 + px + 2] = a.z * sGix[px + 2];
            sSp[c * 96 + px + 3] = a.w * sGix[px + 3];
        }
        __syncthreads();

        // ---- S3: q = u - cvec - sp - bl; exp -------------------------------
        if (tid < 672) {
            #pragma unroll
            for (int j = 0; j < 3; j++) {
                int idx = tid + j * 672;
                int o = idx / 96, px = idx % 96;
                float bl = (sBlP[idx] + sBlP[2016 + idx] + sBlP[4032 + idx]) * sNbI[px];
                float q = sU[idx] - sCv[o] - sSp[idx] - bl;
                sQ[idx] = expf(q);
            }
        }
        __syncthreads();

        // ---- S4: inv-sum (+ final output) ----------------------------------
        if (tid < HW) {
            int px = tid;
            float ss = 0.0f;
            #pragma unroll
            for (int o = 0; o < NC; o++) ss += sQ[o * 96 + px];
            float inv = 1.0f / ss;
            sIv[px] = inv;
            if (it == 4) {
                #pragma unroll
                for (int o = 0; o < NC; o++)
                    out[o * NPIX + y * HW + px] = sQ[o * 96 + px] * inv;
            }
        }
        if (it == 4) break;
        __syncthreads();

        // ---- S5: mix t1, t2 ------------------------------------------------
        if (tid < 336) {
            int og = tid / 48, pp = tid % 48;
            int o0 = og * 3;
            ull t1a[3] = {0, 0, 0}, t2a[3] = {0, 0, 0};
            for (int c = 0; c < NC; c++) {
                ull sv = *(const ull*)(sQ + c * 96 + 2 * pp);
                #pragma unroll
                for (int k = 0; k < 3; k++) {
                    fma2(t1a[k], sv, sW1D[(o0 + k) * NC + c]);
                    fma2(t2a[k], sv, sW2D[(o0 + k) * NC + c]);
                }
            }
            float i0 = sIv[2 * pp], i1 = sIv[2 * pp + 1];
            #pragma unroll
            for (int k = 0; k < 3; k++) {
                sT1[(o0 + k) * 128 + 16 + 2 * pp]     = lo2(t1a[k]) * i0;
                sT1[(o0 + k) * 128 + 16 + 2 * pp + 1] = hi2(t1a[k]) * i1;
                sT2[(o0 + k) * 96 + 2 * pp]           = lo2(t2a[k]) * i0;
                sT2[(o0 + k) * 96 + 2 * pp + 1]       = hi2(t2a[k]) * i1;
            }
        }
        __syncthreads();

        // ---- S6: spX(t1) | moments(t2) -------------------------------------
        if (tid < 504) {
            int c = tid / 24, q4 = tid % 24;
            float w[28];
            const float* base = sT1 + c * 128 + 4 + 4 * q4;
            #pragma unroll
            for (int i = 0; i < 7; i++) *(float4*)(w + 4 * i) = *(const float4*)(base + 4 * i);
            float a0 = 0.f, a1 = 0.f, a2 = 0.f, a3 = 0.f;
            #pragma unroll
            for (int d = 0; d < KW; d++) {
                float k = sKer[d];
                a0 += k * w[d]; a1 += k * w[d + 1]; a2 += k * w[d + 2]; a3 += k * w[d + 3];
            }
            *(float4*)(g_tmpP + (c * TROWS + KR + y) * HW + 4 * q4) = make_float4(a0, a1, a2, a3);
        } else if (tid >= 512 && tid < 708) {
            int u2 = tid - 512;
            int quarter = u2 / 49, r2 = u2 % 49;
            int cg = r2 / 7, rg = r2 % 7;
            int r0 = rg * 3, c0 = cg * 3;
            ull acc[9];
            #pragma unroll
            for (int k = 0; k < 9; k++) acc[k] = 0ull;
            int p0 = quarter * 12;
            for (int p = p0; p < p0 + 12; p++) {
                ull ph0 = *(const ull*)(sPhi + (r0 + 0) * PHS + 2 * p);
                ull ph1 = *(const ull*)(sPhi + (r0 + 1) * PHS + 2 * p);
                ull ph2 = *(const ull*)(sPhi + (r0 + 2) * PHS + 2 * p);
                #pragma unroll
                for (int j = 0; j < 3; j++) {
                    ull sv = *(const ull*)(sT2 + (c0 + j) * 96 + 2 * p);
                    fma2(acc[j * 3 + 0], ph0, sv);
                    fma2(acc[j * 3 + 1], ph1, sv);
                    fma2(acc[j * 3 + 2], ph2, sv);
                }
            }
            #pragma unroll
            for (int j = 0; j < 3; j++)
                #pragma unroll
                for (int i = 0; i < 3; i++)
                    sMomP[quarter * NMOM + (c0 + j) * RD + r0 + i] =
                        lo2(acc[j * 3 + i]) + hi2(acc[j * 3 + i]);
        }
        __syncthreads();
        // ---- S6b: reduce -> mom[wrb] ---------------------------------------
        if (tid < NMOM) {
            float v = sMomP[tid] + sMomP[NMOM + tid]
                    + sMomP[2 * NMOM + tid] + sMomP[3 * NMOM + tid];
            atomicAdd(&g_mom[wrb * NMOM + tid], v);
        }
        gsync();                             // barriers #2..#5
    }
}

// ------------------------------ launch -------------------------------------
extern "C" void kernel_launch(void* const* d_in, const int* in_sizes, int n_in,
                              void* d_out, int out_size) {
    const float* image  = (const float*)d_in[0];
    const float* net_w  = (const float*)d_in[1];
    const float* net_b  = (const float*)d_in[2];
    const float* sp_w   = (const float*)d_in[3];
    const float* sp_b   = (const float*)d_in[4];
    const float* bl_w   = (const float*)d_in[5];
    const float* bl_b   = (const float*)d_in[6];
    const float* comp_w = (const float*)d_in[7];
    const float* comp_b = (const float*)d_in[8];
    float* out = (float*)d_out;

    static int smem_set = 0;
    if (!smem_set) {
        cudaFuncSetAttribute(crf_all, cudaFuncAttributeMaxDynamicSharedMemorySize,
                             SMEM_BYTES);
        smem_set = 1;
    }
    crf_all<<<GRID, TPB, SMEM_BYTES>>>(image, net_w, net_b, sp_w, sp_b,
                                       bl_w, bl_b, comp_w, comp_b, out);
}